// round 5
// baseline (speedup 1.0000x reference)
#include <cuda_runtime.h>
#include <cuda_fp16.h>
#include <mma.h>
#include <math.h>

using namespace nvcuda;

#define NN    4096
#define INF_  512
#define HID   8
#define OUTF  256
#define MAXD  128

// ---------------- scratch (static device globals) ---------------------------
__device__ int    g_deg[NN];
__device__ int    g_nbr[NN * MAXD];
__device__ float  g_phu[NN * HID];    // exp(dst1[j]) * h[j]   (unnormalized)
__device__ float  g_e1[NN];           // exp(dst1[j])
__device__ float  g_qu[NN];           // exp(d2[j]) * h2v[j]   (unnormalized)
__device__ float  g_e2[NN];           // exp(d2[j])
__device__ int    g_rows[2][NN];      // [0]=mask==1 (y1,Wa), [1]=mask==0 (y3,Wc)
__device__ int    g_cnt[2];
__device__ int    g_skip3[NN];        // 1 -> y3[row] never read
__device__ int    g_need2[NN];        // 1 -> y2[row] read by some y3 computation
__device__ __half g_xh [NN * INF_];   // x in fp16
__device__ __half g_y1h[NN * INF_];   // adj   @ x
__device__ __half g_y2h[NN * INF_];   // adj^2 @ x
__device__ __half g_y3h[NN * INF_];   // adj^3 @ x
__device__ __half g_WhA[INF_ * OUTF]; // W_sgc[0:512]     in fp16
__device__ __half g_WhC[INF_ * OUTF]; // W_sgc[1024:1536] in fp16

// ---- fused prelude: build nbr lists | x->fp16 | h=x@W1 chain | W->fp16 -----
__global__ void k_prelude(const float* __restrict__ adj, const float* __restrict__ x,
                          const float* __restrict__ W1, const float* __restrict__ a1,
                          const float* __restrict__ Wsgc) {
    int b = blockIdx.x;
    int t = threadIdx.x;          // 256

    if (b < 4096) {
        int row = b;
        const float4* ar = (const float4*)(adj + (size_t)row * NN);
        float4 v[4];
        int cnt = 0;
#pragma unroll
        for (int i = 0; i < 4; i++) {
            v[i] = ar[t + i * 256];
            cnt += (v[i].x != 0.f) + (v[i].y != 0.f) + (v[i].z != 0.f) + (v[i].w != 0.f);
        }
        __shared__ int sc[256];
        sc[t] = cnt;
        __syncthreads();
        for (int d = 1; d < 256; d <<= 1) {
            int val = (t >= d) ? sc[t - d] : 0;
            __syncthreads();
            if (t >= d) sc[t] += val;
            __syncthreads();
        }
        int pos   = sc[t] - cnt;
        int total = sc[255];
        int* nb = g_nbr + (size_t)row * MAXD;
#pragma unroll
        for (int i = 0; i < 4; i++) {
            int base = (t + i * 256) * 4;
            if (v[i].x != 0.f) { if (pos < MAXD) nb[pos] = base + 0; pos++; }
            if (v[i].y != 0.f) { if (pos < MAXD) nb[pos] = base + 1; pos++; }
            if (v[i].z != 0.f) { if (pos < MAXD) nb[pos] = base + 2; pos++; }
            if (v[i].w != 0.f) { if (pos < MAXD) nb[pos] = base + 3; pos++; }
        }
        if (t == 0) {
            g_deg[row]   = total < MAXD ? total : MAXD;
            g_need2[row] = 0;
        }
        if (row == 0 && t < 2) g_cnt[t] = 0;
    } else if (b < 6144) {
        int i = (b - 4096) * 256 + t;
        float4 v = ((const float4*)x)[i];
        __half2 lo = __floats2half2_rn(v.x, v.y);
        __half2 hi = __floats2half2_rn(v.z, v.w);
        uint2 packed;
        packed.x = *(unsigned*)&lo;
        packed.y = *(unsigned*)&hi;
        ((uint2*)g_xh)[i] = packed;
    } else if (b < 6656) {
        int lane = t & 31;
        int row  = (b - 6144) * 8 + (t >> 5);
        const float* xr = x + (size_t)row * INF_;
        float acc[HID];
#pragma unroll
        for (int f = 0; f < HID; f++) acc[f] = 0.f;
        for (int k = lane; k < INF_; k += 32) {
            float xv = xr[k];
            float4 wA = *(const float4*)(W1 + k * HID);
            float4 wB = *(const float4*)(W1 + k * HID + 4);
            acc[0] += xv * wA.x; acc[1] += xv * wA.y; acc[2] += xv * wA.z; acc[3] += xv * wA.w;
            acc[4] += xv * wB.x; acc[5] += xv * wB.y; acc[6] += xv * wB.z; acc[7] += xv * wB.w;
        }
#pragma unroll
        for (int f = 0; f < HID; f++)
            for (int o = 16; o; o >>= 1) acc[f] += __shfl_xor_sync(0xffffffffu, acc[f], o);
        if (lane == 0) {
            float d = 0.f;
#pragma unroll
            for (int f = 0; f < HID; f++) d += acc[f] * a1[HID + f];
            float e1 = expf(d);
            g_e1[row] = e1;
#pragma unroll
            for (int f = 0; f < HID; f++) g_phu[row * HID + f] = e1 * acc[f];
        }
    } else {
        int which = (b >= 6784);
        int base  = which ? 6784 : 6656;
        const float* src = Wsgc + (which ? (size_t)1024 * OUTF : 0);
        __half* dst = which ? g_WhC : g_WhA;
        int i = (b - base) * 256 + t;
        float4 v = ((const float4*)src)[i];
        __half2 lo = __floats2half2_rn(v.x, v.y);
        __half2 hi = __floats2half2_rn(v.z, v.w);
        uint2 packed;
        packed.x = *(unsigned*)&lo;
        packed.y = *(unsigned*)&hi;
        ((uint2*)dst)[i] = packed;
    }
}

// ---- block-redundant sum of 4096 floats (deterministic order) --------------
__device__ __forceinline__ float block_sum4096(const float* v, int t) {
    __shared__ float sred[8];
    __shared__ float sbc;
    float s = 0.f;
    const float4* v4 = (const float4*)v;
#pragma unroll
    for (int i = 0; i < 4; i++) {
        float4 a = v4[t + i * 256];
        s += (a.x + a.y) + (a.z + a.w);
    }
    for (int o = 16; o; o >>= 1) s += __shfl_xor_sync(0xffffffffu, s, o);
    if ((t & 31) == 0) sred[t >> 5] = s;
    __syncthreads();
    if (t < 32) {
        float r = (t < 8) ? sred[t] : 0.f;
        for (int o = 4; o; o >>= 1) r += __shfl_xor_sync(0xffffffffu, r, o);
        if (t == 0) sbc = r;
    }
    __syncthreads();
    return sbc;
}

// --- gat1: h1 = elu((adj@phu)/S1); h2 = h1@W2; e2 = exp(h2*a2[1]); qu=e2*h2 -
__global__ void k_gat1(const float* __restrict__ W2, const float* __restrict__ a2) {
    int t    = threadIdx.x;
    float S1 = block_sum4096(g_e1, t);

    int lane = t & 31;
    int row  = blockIdx.x * 8 + (t >> 5);
    int deg  = g_deg[row];
    const int* nb = g_nbr + (size_t)row * MAXD;

    float acc[HID];
#pragma unroll
    for (int f = 0; f < HID; f++) acc[f] = 0.f;

    for (int k = lane; k < deg; k += 32) {
        int j = nb[k];
        float4 A = *(const float4*)(g_phu + j * HID);
        float4 B = *(const float4*)(g_phu + j * HID + 4);
        acc[0] += A.x; acc[1] += A.y; acc[2] += A.z; acc[3] += A.w;
        acc[4] += B.x; acc[5] += B.y; acc[6] += B.z; acc[7] += B.w;
    }
#pragma unroll
    for (int f = 0; f < HID; f++)
        for (int o = 16; o; o >>= 1) acc[f] += __shfl_xor_sync(0xffffffffu, acc[f], o);

    if (lane == 0) {
        float invS = 1.f / S1;
        float h2 = 0.f;
#pragma unroll
        for (int f = 0; f < HID; f++) {
            float v = acc[f] * invS;
            v = v > 0.f ? v : (expf(v) - 1.f);   // elu
            h2 += v * W2[f];
        }
        float e2 = expf(h2 * a2[1]);
        g_e2[row] = e2;
        g_qu[row] = e2 * h2;
    }
}

// ---- mask: s2 = (adj@qu)/S2; elu; threshold; row lists; SpMM gating --------
__global__ void k_mask() {
    int t    = threadIdx.x;
    float S2 = block_sum4096(g_e2, t);

    int lane = t & 31;
    int row  = blockIdx.x * 8 + (t >> 5);
    int deg  = g_deg[row];
    const int* nb = g_nbr + (size_t)row * MAXD;

    float s = 0.f;
    for (int k = lane; k < deg; k += 32) s += g_qu[nb[k]];
    for (int o = 16; o; o >>= 1) s += __shfl_xor_sync(0xffffffffu, s, o);

    int which;
    if (lane == 0) {
        float s2 = s / S2;
        float sc = s2 > 0.f ? s2 : (expf(s2) - 1.f);   // elu
        which = (sc > 0.7f) ? 0 : 1;
        g_skip3[row] = (which == 0);
        int pos = atomicAdd(&g_cnt[which], 1);
        g_rows[which][pos] = row;
    }
    which = __shfl_sync(0xffffffffu, which, 0);
    if (which == 1) {
        for (int k = lane; k < deg; k += 32) g_need2[nb[k]] = 1;  // idempotent
    }
}

// ---- tensor-core SpMM: y[i] = sum_{j in N(i)} src[j] via one-hot HMMA ------
// Block: 128 thr (4 warps), 16 dest rows x 256 cols. Grid (256, 2).
// Per 16-entry chunk: A(16x16) one-hot dest map, B(16x256) gathered rows,
// C += A@B with fp32 accumulators.
#define RPB   16
#define CPB   256
#define LDB_H 264    // halves per B row (256 + 8 pad)
#define LDS_F 260    // floats per stage row (256 + 4 pad)

__global__ void k_spmm_tc(int mode) {
    const __half* __restrict__ src =
        (mode == 0) ? g_xh : ((mode == 1) ? g_y1h : g_y2h);
    __half* dst = (mode == 0) ? g_y1h : ((mode == 1) ? g_y2h : g_y3h);

    // carve: lst 8192B | Bs 8448B | As 512B ; stage(16640B f32) aliases lst+Bs
    __shared__ __align__(16) char sm[2048 * 4 + RPB * LDB_H * 2 + RPB * 16 * 2 + 64];
    int*    lst   = (int*)sm;
    __half* Bs    = (__half*)(sm + 8192);
    __half* As    = (__half*)(sm + 8192 + RPB * LDB_H * 2);
    float*  stage = (float*)sm;
    __shared__ int degs[RPB], offs[RPB + 1], sgate[RPB];

    int rt = blockIdx.x * RPB;
    int cb = blockIdx.y * CPB;
    int t  = threadIdx.x;        // 128
    int warp = t >> 5;

    if (t < RPB) {
        int row  = rt + t;
        int gate = 1;
        if (mode == 1 && !g_need2[row]) gate = 0;
        if (mode == 2 &&  g_skip3[row]) gate = 0;
        sgate[t] = gate;
        degs[t]  = gate ? g_deg[row] : 0;
    }
    __syncthreads();
    if (t == 0) {
        int s = 0;
        for (int i = 0; i < RPB; i++) { offs[i] = s; s += degs[i]; }
        offs[RPB] = s;
    }
    __syncthreads();
    int L  = offs[RPB];
    int Lp = (L + 15) & ~15;

    for (int r = 0; r < RPB; r++) {
        int d = degs[r], o = offs[r];
        const int* nb = g_nbr + (size_t)(rt + r) * MAXD;
        for (int i = t; i < d; i += 128) lst[o + i] = nb[i] | (r << 16);
    }
    for (int i = L + t; i < Lp; i += 128) lst[i] = (255 << 16);   // dead entry
    __syncthreads();

    wmma::fragment<wmma::accumulator, 16, 16, 16, float> cfr[4];
#pragma unroll
    for (int j = 0; j < 4; j++) wmma::fill_fragment(cfr[j], 0.f);

    int nk = Lp >> 4;
    for (int ks = 0; ks < nk; ks++) {
        const int* le = lst + (ks << 4);
        // gather 16 source-row slices (256 halves each)
#pragma unroll
        for (int u = 0; u < 4; u++) {
            int idx = u * 128 + t;        // 0..511
            int er  = idx >> 5;           // entry
            int ch  = idx & 31;           // uint4 chunk
            int e   = le[er];
            int srow = e & 0xFFFF;
            uint4 v = *(const uint4*)(src + (size_t)srow * INF_ + cb + ch * 8);
            *(uint4*)(Bs + er * LDB_H + ch * 8) = v;
        }
        // build one-hot A (dest i gets entry k iff k's destIdx == i)
#pragma unroll
        for (int u = 0; u < 2; u++) {
            int idx = u * 128 + t;        // 0..255
            int i = idx >> 4, k = idx & 15;
            int di = le[k] >> 16;
            As[i * 16 + k] = (di == i) ? __float2half(1.f) : __float2half(0.f);
        }
        __syncthreads();

        wmma::fragment<wmma::matrix_a, 16, 16, 16, __half, wmma::row_major> afr;
        wmma::load_matrix_sync(afr, As, 16);
#pragma unroll
        for (int j = 0; j < 4; j++) {
            wmma::fragment<wmma::matrix_b, 16, 16, 16, __half, wmma::row_major> bfr;
            wmma::load_matrix_sync(bfr, Bs + warp * 64 + j * 16, LDB_H);
            wmma::mma_sync(cfr[j], afr, bfr, cfr[j]);
        }
        __syncthreads();
    }

    // stage fp32 results (aliases lst/Bs; safe after final sync)
#pragma unroll
    for (int j = 0; j < 4; j++)
        wmma::store_matrix_sync(stage + warp * 64 + j * 16, cfr[j], LDS_F,
                                wmma::mem_row_major);
    __syncthreads();

    // convert + store (skip gated rows)
#pragma unroll
    for (int u = 0; u < 8; u++) {
        int idx = u * 128 + t;            // 0..1023
        int r = idx >> 6, c4 = idx & 63;
        if (sgate[r]) {
            float4 v = *(const float4*)(stage + r * LDS_F + c4 * 4);
            __half2 h0 = __floats2half2_rn(v.x, v.y);
            __half2 h1 = __floats2half2_rn(v.z, v.w);
            uint2 p;
            p.x = *(unsigned*)&h0;
            p.y = *(unsigned*)&h1;
            *(uint2*)(dst + (size_t)(rt + r) * INF_ + cb + c4 * 4) = p;
        }
    }
}

// ---- routed GEMM via wmma (HMMA fp16 -> fp32 acc) --------------------------
#define GLDA_S 72    // halves (64 + 8 pad)
#define GLDB_S 136   // halves (128 + 8 pad)
#define GLDS_F 132   // floats (128 + 4 pad)

__global__ void k_gemm(const float* __restrict__ bias, float* __restrict__ out) {
    __shared__ __align__(16) char buf[64 * GLDS_F * 4];
    __shared__ int ridx[64];

    __half* sA = (__half*)buf;
    __half* sB = (__half*)(buf + 64 * GLDA_S * 2);
    float*  stage = (float*)buf;

    int which = blockIdx.z;
    int cnt   = g_cnt[which];
    int rbase = blockIdx.x * 64;
    if (rbase >= cnt) return;

    const __half* A = which ? g_y3h : g_y1h;
    const __half* W = which ? g_WhC : g_WhA;
    int cb = blockIdx.y * 128;

    int t = threadIdx.x;   // 256
    int warp = t >> 5;
    int wrow = warp & 3;
    int wcol = warp >> 2;

    if (t < 64) {
        int li = rbase + t;
        ridx[t] = (li < cnt) ? g_rows[which][li] : -1;
    }
    __syncthreads();

    int myArow0 = ridx[t >> 2];
    const __half* aSrc = A + (size_t)(myArow0 < 0 ? 0 : myArow0) * INF_;
    int apart = t & 3;

    wmma::fragment<wmma::accumulator, 16, 16, 16, float> cfr[4];
#pragma unroll
    for (int j = 0; j < 4; j++) wmma::fill_fragment(cfr[j], 0.f);

    for (int kc = 0; kc < INF_; kc += 64) {
#pragma unroll
        for (int u = 0; u < 2; u++) {
            int chunk = apart * 2 + u;
            uint4 v = *(const uint4*)(aSrc + kc + chunk * 8);
            *(uint4*)(sA + (t >> 2) * GLDA_S + chunk * 8) = v;
        }
#pragma unroll
        for (int v4 = 0; v4 < 4; v4++) {
            int idx = v4 * 256 + t;
            int krow = idx >> 4, chunk = idx & 15;
            uint4 v = *(const uint4*)(W + (size_t)(kc + krow) * OUTF + cb + chunk * 8);
            *(uint4*)(sB + krow * GLDB_S + chunk * 8) = v;
        }
        __syncthreads();

#pragma unroll
        for (int ks = 0; ks < 4; ks++) {
            wmma::fragment<wmma::matrix_a, 16, 16, 16, __half, wmma::row_major> afr;
            wmma::load_matrix_sync(afr, sA + wrow * 16 * GLDA_S + ks * 16, GLDA_S);
#pragma unroll
            for (int j = 0; j < 4; j++) {
                wmma::fragment<wmma::matrix_b, 16, 16, 16, __half, wmma::row_major> bfr;
                wmma::load_matrix_sync(bfr, sB + ks * 16 * GLDB_S + wcol * 64 + j * 16, GLDB_S);
                wmma::mma_sync(cfr[j], afr, bfr, cfr[j]);
            }
        }
        __syncthreads();
    }

#pragma unroll
    for (int j = 0; j < 4; j++)
        wmma::store_matrix_sync(stage + wrow * 16 * GLDS_F + wcol * 64 + j * 16,
                                cfr[j], GLDS_F, wmma::mem_row_major);
    __syncthreads();

#pragma unroll
    for (int w = 0; w < 8; w++) {
        int idx = w * 256 + t;
        int rl = idx >> 5, chunk = idx & 31;
        int col = chunk * 4;
        int grow = ridx[rl];
        if (grow >= 0) {
            float4 v = *(const float4*)(stage + rl * GLDS_F + col);
            float4 bv = *(const float4*)(bias + cb + col);
            v.x += bv.x; v.y += bv.y; v.z += bv.z; v.w += bv.w;
            *(float4*)(out + (size_t)grow * OUTF + cb + col) = v;
        }
    }
}

// ---------------- launcher --------------------------------------------------
extern "C" void kernel_launch(void* const* d_in, const int* in_sizes, int n_in,
                              void* d_out, int out_size) {
    const float* x    = (const float*)d_in[0];
    const float* adj  = (const float*)d_in[1];
    const float* W1   = (const float*)d_in[2];
    const float* a1   = (const float*)d_in[3];
    const float* W2   = (const float*)d_in[4];
    const float* a2   = (const float*)d_in[5];
    const float* Wsgc = (const float*)d_in[6];
    const float* bsgc = (const float*)d_in[7];
    float* out = (float*)d_out;

    k_prelude<<<6912, 256>>>(adj, x, W1, a1, Wsgc);
    k_gat1<<<NN / 8, 256>>>(W2, a2);
    k_mask<<<NN / 8, 256>>>();
    k_spmm_tc<<<dim3(256, 2), 128>>>(0);   // y1 = adj   @ x
    k_spmm_tc<<<dim3(256, 2), 128>>>(1);   // y2 = adj^2 @ x (need2-gated)
    k_spmm_tc<<<dim3(256, 2), 128>>>(2);   // y3 = adj^3 @ x (skip3-gated)
    k_gemm<<<dim3(64, 2, 2), 256>>>(bsgc, out);
}

// round 6
// speedup vs baseline: 2.3055x; 2.3055x over previous
#include <cuda_runtime.h>
#include <cuda_fp16.h>
#include <mma.h>
#include <math.h>

using namespace nvcuda;

#define NN    4096
#define INF_  512
#define HID   8
#define OUTF  256
#define MAXD  128

// ---------------- scratch (static device globals) ---------------------------
__device__ int    g_deg[NN];
__device__ int    g_nbr[NN * MAXD];
__device__ float  g_phu[NN * HID];    // exp(dst1[j]) * h[j]   (unnormalized)
__device__ float  g_e1[NN];           // exp(dst1[j])
__device__ float  g_qu[NN];           // exp(d2[j]) * h2v[j]   (unnormalized)
__device__ float  g_e2[NN];           // exp(d2[j])
__device__ int    g_rows[2][NN];      // [0]=mask==1 (y1,Wa), [1]=mask==0 (y3,Wc)
__device__ int    g_cnt[2];
__device__ int    g_skip3[NN];        // 1 -> y3[row] never read
__device__ int    g_need2[NN];        // 1 -> y2[row] read by some y3 computation
__device__ __half g_xh [NN * INF_];   // x in fp16
__device__ __half g_y1h[NN * INF_];   // adj   @ x
__device__ __half g_y2h[NN * INF_];   // adj^2 @ x
__device__ __half g_y3h[NN * INF_];   // adj^3 @ x
__device__ __half g_WhA[INF_ * OUTF]; // W_sgc[0:512]     in fp16
__device__ __half g_WhC[INF_ * OUTF]; // W_sgc[1024:1536] in fp16

// ---- fused prelude: build nbr lists | x->fp16 | h=x@W1 chain | W->fp16 -----
__global__ void k_prelude(const float* __restrict__ adj, const float* __restrict__ x,
                          const float* __restrict__ W1, const float* __restrict__ a1,
                          const float* __restrict__ Wsgc) {
    int b = blockIdx.x;
    int t = threadIdx.x;          // 256

    if (b < 4096) {
        int row = b;
        const float4* ar = (const float4*)(adj + (size_t)row * NN);
        float4 v[4];
        int cnt = 0;
#pragma unroll
        for (int i = 0; i < 4; i++) {
            v[i] = ar[t + i * 256];
            cnt += (v[i].x != 0.f) + (v[i].y != 0.f) + (v[i].z != 0.f) + (v[i].w != 0.f);
        }
        __shared__ int sc[256];
        sc[t] = cnt;
        __syncthreads();
        for (int d = 1; d < 256; d <<= 1) {
            int val = (t >= d) ? sc[t - d] : 0;
            __syncthreads();
            if (t >= d) sc[t] += val;
            __syncthreads();
        }
        int pos   = sc[t] - cnt;
        int total = sc[255];
        int* nb = g_nbr + (size_t)row * MAXD;
#pragma unroll
        for (int i = 0; i < 4; i++) {
            int base = (t + i * 256) * 4;
            if (v[i].x != 0.f) { if (pos < MAXD) nb[pos] = base + 0; pos++; }
            if (v[i].y != 0.f) { if (pos < MAXD) nb[pos] = base + 1; pos++; }
            if (v[i].z != 0.f) { if (pos < MAXD) nb[pos] = base + 2; pos++; }
            if (v[i].w != 0.f) { if (pos < MAXD) nb[pos] = base + 3; pos++; }
        }
        if (t == 0) {
            g_deg[row]   = total < MAXD ? total : MAXD;
            g_need2[row] = 0;
        }
        if (row == 0 && t < 2) g_cnt[t] = 0;
    } else if (b < 6144) {
        int i = (b - 4096) * 256 + t;
        float4 v = ((const float4*)x)[i];
        __half2 lo = __floats2half2_rn(v.x, v.y);
        __half2 hi = __floats2half2_rn(v.z, v.w);
        uint2 packed;
        packed.x = *(unsigned*)&lo;
        packed.y = *(unsigned*)&hi;
        ((uint2*)g_xh)[i] = packed;
    } else if (b < 6656) {
        int lane = t & 31;
        int row  = (b - 6144) * 8 + (t >> 5);
        const float* xr = x + (size_t)row * INF_;
        float acc[HID];
#pragma unroll
        for (int f = 0; f < HID; f++) acc[f] = 0.f;
        for (int k = lane; k < INF_; k += 32) {
            float xv = xr[k];
            float4 wA = *(const float4*)(W1 + k * HID);
            float4 wB = *(const float4*)(W1 + k * HID + 4);
            acc[0] += xv * wA.x; acc[1] += xv * wA.y; acc[2] += xv * wA.z; acc[3] += xv * wA.w;
            acc[4] += xv * wB.x; acc[5] += xv * wB.y; acc[6] += xv * wB.z; acc[7] += xv * wB.w;
        }
#pragma unroll
        for (int f = 0; f < HID; f++)
            for (int o = 16; o; o >>= 1) acc[f] += __shfl_xor_sync(0xffffffffu, acc[f], o);
        if (lane == 0) {
            float d = 0.f;
#pragma unroll
            for (int f = 0; f < HID; f++) d += acc[f] * a1[HID + f];
            float e1 = expf(d);
            g_e1[row] = e1;
#pragma unroll
            for (int f = 0; f < HID; f++) g_phu[row * HID + f] = e1 * acc[f];
        }
    } else {
        int which = (b >= 6784);
        int base  = which ? 6784 : 6656;
        const float* src = Wsgc + (which ? (size_t)1024 * OUTF : 0);
        __half* dst = which ? g_WhC : g_WhA;
        int i = (b - base) * 256 + t;
        float4 v = ((const float4*)src)[i];
        __half2 lo = __floats2half2_rn(v.x, v.y);
        __half2 hi = __floats2half2_rn(v.z, v.w);
        uint2 packed;
        packed.x = *(unsigned*)&lo;
        packed.y = *(unsigned*)&hi;
        ((uint2*)dst)[i] = packed;
    }
}

// ---- block-redundant sum of 4096 floats (deterministic order) --------------
__device__ __forceinline__ float block_sum4096(const float* v, int t) {
    __shared__ float sred[8];
    __shared__ float sbc;
    float s = 0.f;
    const float4* v4 = (const float4*)v;
#pragma unroll
    for (int i = 0; i < 4; i++) {
        float4 a = v4[t + i * 256];
        s += (a.x + a.y) + (a.z + a.w);
    }
    for (int o = 16; o; o >>= 1) s += __shfl_xor_sync(0xffffffffu, s, o);
    if ((t & 31) == 0) sred[t >> 5] = s;
    __syncthreads();
    if (t < 32) {
        float r = (t < 8) ? sred[t] : 0.f;
        for (int o = 4; o; o >>= 1) r += __shfl_xor_sync(0xffffffffu, r, o);
        if (t == 0) sbc = r;
    }
    __syncthreads();
    return sbc;
}

// ---- SpMM body: 4 rows per block, 64 threads/row, 16B/thread ---------------
// mode 0: xh -> y1h ; mode 1: y1h -> y2h (need2) ; mode 2: y2h -> y3h (!skip3)
__device__ __forceinline__ void spmm_rows4(int mode, int blk) {
    const __half* __restrict__ src =
        (mode == 0) ? g_xh : ((mode == 1) ? g_y1h : g_y2h);
    __half* dst = (mode == 0) ? g_y1h : ((mode == 1) ? g_y2h : g_y3h);

    __shared__ int nbs[4][MAXD];
    int g   = threadIdx.x >> 6;     // 0..3 row group
    int lt  = threadIdx.x & 63;
    int row = blk * 4 + g;

    int gate = 1;
    if (mode == 1 && !g_need2[row]) gate = 0;
    if (mode == 2 &&  g_skip3[row]) gate = 0;
    int deg = gate ? g_deg[row] : 0;

    for (int i = lt; i < deg; i += 64) nbs[g][i] = g_nbr[(size_t)row * MAXD + i];
    __syncthreads();

    int c = lt << 3;                // 64 threads * 8 halves = 512 cols
    float acc[8];
#pragma unroll
    for (int i = 0; i < 8; i++) acc[i] = 0.f;

    int k = 0;
    for (; k + 8 <= deg; k += 8) {
        uint4 r[8];
#pragma unroll
        for (int u = 0; u < 8; u++)
            r[u] = *(const uint4*)(src + (size_t)nbs[g][k + u] * INF_ + c);
#pragma unroll
        for (int u = 0; u < 8; u++) {
            float2 f0 = __half22float2(*(__half2*)&r[u].x);
            float2 f1 = __half22float2(*(__half2*)&r[u].y);
            float2 f2 = __half22float2(*(__half2*)&r[u].z);
            float2 f3 = __half22float2(*(__half2*)&r[u].w);
            acc[0] += f0.x; acc[1] += f0.y; acc[2] += f1.x; acc[3] += f1.y;
            acc[4] += f2.x; acc[5] += f2.y; acc[6] += f3.x; acc[7] += f3.y;
        }
    }
    for (; k < deg; k++) {
        uint4 rv = *(const uint4*)(src + (size_t)nbs[g][k] * INF_ + c);
        float2 f0 = __half22float2(*(__half2*)&rv.x);
        float2 f1 = __half22float2(*(__half2*)&rv.y);
        float2 f2 = __half22float2(*(__half2*)&rv.z);
        float2 f3 = __half22float2(*(__half2*)&rv.w);
        acc[0] += f0.x; acc[1] += f0.y; acc[2] += f1.x; acc[3] += f1.y;
        acc[4] += f2.x; acc[5] += f2.y; acc[6] += f3.x; acc[7] += f3.y;
    }

    if (gate) {
        uint4 packed;
        __half2 h0 = __floats2half2_rn(acc[0], acc[1]);
        __half2 h1 = __floats2half2_rn(acc[2], acc[3]);
        __half2 h2 = __floats2half2_rn(acc[4], acc[5]);
        __half2 h3 = __floats2half2_rn(acc[6], acc[7]);
        packed.x = *(unsigned*)&h0; packed.y = *(unsigned*)&h1;
        packed.z = *(unsigned*)&h2; packed.w = *(unsigned*)&h3;
        *(uint4*)(dst + (size_t)row * INF_ + c) = packed;
    }
}

// ---- gat1 body: h1=elu((adj@phu)/S1); h2=h1@W2; e2=exp(h2*a2[1]); qu=e2*h2 -
__device__ __forceinline__ void gat1_body(int blk, const float* __restrict__ W2,
                                          const float* __restrict__ a2) {
    int t    = threadIdx.x;
    float S1 = block_sum4096(g_e1, t);

    int lane = t & 31;
    int row  = blk * 8 + (t >> 5);
    int deg  = g_deg[row];
    const int* nb = g_nbr + (size_t)row * MAXD;

    float acc[HID];
#pragma unroll
    for (int f = 0; f < HID; f++) acc[f] = 0.f;

    for (int k = lane; k < deg; k += 32) {
        int j = nb[k];
        float4 A = *(const float4*)(g_phu + j * HID);
        float4 B = *(const float4*)(g_phu + j * HID + 4);
        acc[0] += A.x; acc[1] += A.y; acc[2] += A.z; acc[3] += A.w;
        acc[4] += B.x; acc[5] += B.y; acc[6] += B.z; acc[7] += B.w;
    }
#pragma unroll
    for (int f = 0; f < HID; f++)
        for (int o = 16; o; o >>= 1) acc[f] += __shfl_xor_sync(0xffffffffu, acc[f], o);

    if (lane == 0) {
        float invS = 1.f / S1;
        float h2 = 0.f;
#pragma unroll
        for (int f = 0; f < HID; f++) {
            float v = acc[f] * invS;
            v = v > 0.f ? v : (expf(v) - 1.f);   // elu
            h2 += v * W2[f];
        }
        float e2 = expf(h2 * a2[1]);
        g_e2[row] = e2;
        g_qu[row] = e2 * h2;
    }
}

// ---- GEMM body via wmma (HMMA fp16 -> fp32 acc) ----------------------------
#define GLDA_S 72    // halves (64 + 8 pad)
#define GLDB_S 136   // halves (128 + 8 pad)
#define GLDS_F 132   // floats (128 + 4 pad)

__device__ __forceinline__ void gemm_body(int which, int bx, int by,
                                          const float* __restrict__ bias,
                                          float* __restrict__ out) {
    __shared__ __align__(16) char buf[64 * GLDS_F * 4];
    __shared__ int ridx[64];

    __half* sA = (__half*)buf;
    __half* sB = (__half*)(buf + 64 * GLDA_S * 2);
    float*  stage = (float*)buf;

    int cnt   = g_cnt[which];
    int rbase = bx * 64;
    if (rbase >= cnt) return;

    const __half* A = which ? g_y3h : g_y1h;
    const __half* W = which ? g_WhC : g_WhA;
    int cb = by * 128;

    int t = threadIdx.x;   // 256
    int warp = t >> 5;
    int wrow = warp & 3;
    int wcol = warp >> 2;

    if (t < 64) {
        int li = rbase + t;
        ridx[t] = (li < cnt) ? g_rows[which][li] : -1;
    }
    __syncthreads();

    int myArow0 = ridx[t >> 2];
    const __half* aSrc = A + (size_t)(myArow0 < 0 ? 0 : myArow0) * INF_;
    int apart = t & 3;

    wmma::fragment<wmma::accumulator, 16, 16, 16, float> cfr[4];
#pragma unroll
    for (int j = 0; j < 4; j++) wmma::fill_fragment(cfr[j], 0.f);

    for (int kc = 0; kc < INF_; kc += 64) {
#pragma unroll
        for (int u = 0; u < 2; u++) {
            int chunk = apart * 2 + u;
            uint4 v = *(const uint4*)(aSrc + kc + chunk * 8);
            *(uint4*)(sA + (t >> 2) * GLDA_S + chunk * 8) = v;
        }
#pragma unroll
        for (int v4 = 0; v4 < 4; v4++) {
            int idx = v4 * 256 + t;
            int krow = idx >> 4, chunk = idx & 15;
            uint4 v = *(const uint4*)(W + (size_t)(kc + krow) * OUTF + cb + chunk * 8);
            *(uint4*)(sB + krow * GLDB_S + chunk * 8) = v;
        }
        __syncthreads();

#pragma unroll
        for (int ks = 0; ks < 4; ks++) {
            wmma::fragment<wmma::matrix_a, 16, 16, 16, __half, wmma::row_major> afr;
            wmma::load_matrix_sync(afr, sA + wrow * 16 * GLDA_S + ks * 16, GLDA_S);
#pragma unroll
            for (int j = 0; j < 4; j++) {
                wmma::fragment<wmma::matrix_b, 16, 16, 16, __half, wmma::row_major> bfr;
                wmma::load_matrix_sync(bfr, sB + ks * 16 * GLDB_S + wcol * 64 + j * 16, GLDB_S);
                wmma::mma_sync(cfr[j], afr, bfr, cfr[j]);
            }
        }
        __syncthreads();
    }

#pragma unroll
    for (int j = 0; j < 4; j++)
        wmma::store_matrix_sync(stage + wrow * 16 * GLDS_F + wcol * 64 + j * 16,
                                cfr[j], GLDS_F, wmma::mem_row_major);
    __syncthreads();

#pragma unroll
    for (int w = 0; w < 8; w++) {
        int idx = w * 256 + t;
        int rl = idx >> 5, chunk = idx & 31;
        int col = chunk * 4;
        int grow = ridx[rl];
        if (grow >= 0) {
            float4 v = *(const float4*)(stage + rl * GLDS_F + col);
            float4 bv = *(const float4*)(bias + cb + col);
            v.x += bv.x; v.y += bv.y; v.z += bv.z; v.w += bv.w;
            *(float4*)(out + (size_t)grow * OUTF + cb + col) = v;
        }
    }
}

// ---- fused launch 2: spmm pass0 [0,1024) | gat1 [1024,1536) ----------------
__global__ void k_sp0_gat1(const float* __restrict__ W2, const float* __restrict__ a2) {
    if (blockIdx.x < 1024) spmm_rows4(0, blockIdx.x);
    else                   gat1_body(blockIdx.x - 1024, W2, a2);
}

// ---- mask: s2 = (adj@qu)/S2; elu; threshold; row lists; SpMM gating --------
__global__ void k_mask() {
    int t    = threadIdx.x;
    float S2 = block_sum4096(g_e2, t);

    int lane = t & 31;
    int row  = blockIdx.x * 8 + (t >> 5);
    int deg  = g_deg[row];
    const int* nb = g_nbr + (size_t)row * MAXD;

    float s = 0.f;
    for (int k = lane; k < deg; k += 32) s += g_qu[nb[k]];
    for (int o = 16; o; o >>= 1) s += __shfl_xor_sync(0xffffffffu, s, o);

    int which;
    if (lane == 0) {
        float s2 = s / S2;
        float sc = s2 > 0.f ? s2 : (expf(s2) - 1.f);   // elu
        which = (sc > 0.7f) ? 0 : 1;
        g_skip3[row] = (which == 0);
        int pos = atomicAdd(&g_cnt[which], 1);
        g_rows[which][pos] = row;
    }
    which = __shfl_sync(0xffffffffu, which, 0);
    if (which == 1) {
        for (int k = lane; k < deg; k += 32) g_need2[nb[k]] = 1;  // idempotent
    }
}

// ---- launch 4: spmm pass1 --------------------------------------------------
__global__ void k_spmm4(int mode) {
    spmm_rows4(mode, blockIdx.x);
}

// ---- fused launch 5: spmm pass2 [0,1024) | gemm which=0 [1024,1152) --------
__global__ void k_sp2_gemm0(const float* __restrict__ bias, float* __restrict__ out) {
    if (blockIdx.x < 1024) {
        spmm_rows4(2, blockIdx.x);
    } else {
        int b = blockIdx.x - 1024;        // 0..127
        gemm_body(0, b & 63, b >> 6, bias, out);
    }
}

// ---- launch 6: gemm which=1 ------------------------------------------------
__global__ void k_gemm1(const float* __restrict__ bias, float* __restrict__ out) {
    gemm_body(1, blockIdx.x, blockIdx.y, bias, out);
}

// ---------------- launcher --------------------------------------------------
extern "C" void kernel_launch(void* const* d_in, const int* in_sizes, int n_in,
                              void* d_out, int out_size) {
    const float* x    = (const float*)d_in[0];
    const float* adj  = (const float*)d_in[1];
    const float* W1   = (const float*)d_in[2];
    const float* a1   = (const float*)d_in[3];
    const float* W2   = (const float*)d_in[4];
    const float* a2   = (const float*)d_in[5];
    const float* Wsgc = (const float*)d_in[6];
    const float* bsgc = (const float*)d_in[7];
    float* out = (float*)d_out;

    k_prelude<<<6912, 256>>>(adj, x, W1, a1, Wsgc);
    k_sp0_gat1<<<1536, 256>>>(W2, a2);       // y1 = adj@x  ||  gat1
    k_mask<<<NN / 8, 256>>>();
    k_spmm4<<<1024, 256>>>(1);               // y2 = adj^2@x (need2-gated)
    k_sp2_gemm0<<<1152, 256>>>(bsgc, out);   // y3 = adj^3@x || gemm(mask==1)
    k_gemm1<<<dim3(64, 2), 256>>>(bsgc, out);// gemm(mask==0)
}

// round 7
// speedup vs baseline: 2.4096x; 1.0451x over previous
#include <cuda_runtime.h>
#include <cuda_fp16.h>
#include <mma.h>
#include <math.h>

using namespace nvcuda;

#define NN    4096
#define INF_  512
#define HID   8
#define OUTF  256
#define MAXD  128

// ---------------- scratch (static device globals) ---------------------------
__device__ int    g_deg[NN];
__device__ int    g_nbr[NN * MAXD];
__device__ float  g_phu[NN * HID];    // exp(dst1[j]) * h[j]   (unnormalized)
__device__ float  g_e1[NN];           // exp(dst1[j])
__device__ float  g_qu[NN];           // exp(d2[j]) * h2v[j]   (unnormalized)
__device__ float  g_e2[NN];           // exp(d2[j])
__device__ int    g_rows[2][NN];      // [0]=mask==1 (y1,Wa), [1]=mask==0 (y3,Wc)
__device__ int    g_cnt[2];
__device__ int    g_skip3[NN];        // 1 -> y3[row] never read
__device__ __half g_xh [NN * INF_];   // x in fp16
__device__ __half g_y1h[NN * INF_];   // adj   @ x
__device__ __half g_y2h[NN * INF_];   // adj^2 @ x
__device__ __half g_y3h[NN * INF_];   // adj^3 @ x
__device__ __half g_WhA[INF_ * OUTF]; // W_sgc[0:512]     in fp16
__device__ __half g_WhC[INF_ * OUTF]; // W_sgc[1024:1536] in fp16

// ---- fused prelude: build nbr lists | x->fp16 | h=x@W1 chain | W->fp16 -----
__global__ void k_prelude(const float* __restrict__ adj, const float* __restrict__ x,
                          const float* __restrict__ W1, const float* __restrict__ a1,
                          const float* __restrict__ Wsgc) {
    int b = blockIdx.x;
    int t = threadIdx.x;          // 256

    if (b < 4096) {
        int row = b;
        const float4* ar = (const float4*)(adj + (size_t)row * NN);
        float4 v[4];
        int cnt = 0;
#pragma unroll
        for (int i = 0; i < 4; i++) {
            v[i] = ar[t + i * 256];
            cnt += (v[i].x != 0.f) + (v[i].y != 0.f) + (v[i].z != 0.f) + (v[i].w != 0.f);
        }
        __shared__ int sc[256];
        sc[t] = cnt;
        __syncthreads();
        for (int d = 1; d < 256; d <<= 1) {
            int val = (t >= d) ? sc[t - d] : 0;
            __syncthreads();
            if (t >= d) sc[t] += val;
            __syncthreads();
        }
        int pos   = sc[t] - cnt;
        int total = sc[255];
        int* nb = g_nbr + (size_t)row * MAXD;
#pragma unroll
        for (int i = 0; i < 4; i++) {
            int base = (t + i * 256) * 4;
            if (v[i].x != 0.f) { if (pos < MAXD) nb[pos] = base + 0; pos++; }
            if (v[i].y != 0.f) { if (pos < MAXD) nb[pos] = base + 1; pos++; }
            if (v[i].z != 0.f) { if (pos < MAXD) nb[pos] = base + 2; pos++; }
            if (v[i].w != 0.f) { if (pos < MAXD) nb[pos] = base + 3; pos++; }
        }
        if (t == 0) g_deg[row] = total < MAXD ? total : MAXD;
        if (row == 0 && t < 2) g_cnt[t] = 0;
    } else if (b < 6144) {
        int i = (b - 4096) * 256 + t;
        float4 v = ((const float4*)x)[i];
        __half2 lo = __floats2half2_rn(v.x, v.y);
        __half2 hi = __floats2half2_rn(v.z, v.w);
        uint2 packed;
        packed.x = *(unsigned*)&lo;
        packed.y = *(unsigned*)&hi;
        ((uint2*)g_xh)[i] = packed;
    } else if (b < 6656) {
        int lane = t & 31;
        int row  = (b - 6144) * 8 + (t >> 5);
        const float* xr = x + (size_t)row * INF_;
        float acc[HID];
#pragma unroll
        for (int f = 0; f < HID; f++) acc[f] = 0.f;
        for (int k = lane; k < INF_; k += 32) {
            float xv = xr[k];
            float4 wA = *(const float4*)(W1 + k * HID);
            float4 wB = *(const float4*)(W1 + k * HID + 4);
            acc[0] += xv * wA.x; acc[1] += xv * wA.y; acc[2] += xv * wA.z; acc[3] += xv * wA.w;
            acc[4] += xv * wB.x; acc[5] += xv * wB.y; acc[6] += xv * wB.z; acc[7] += xv * wB.w;
        }
#pragma unroll
        for (int f = 0; f < HID; f++)
            for (int o = 16; o; o >>= 1) acc[f] += __shfl_xor_sync(0xffffffffu, acc[f], o);
        if (lane == 0) {
            float d = 0.f;
#pragma unroll
            for (int f = 0; f < HID; f++) d += acc[f] * a1[HID + f];
            float e1 = expf(d);
            g_e1[row] = e1;
#pragma unroll
            for (int f = 0; f < HID; f++) g_phu[row * HID + f] = e1 * acc[f];
        }
    } else {
        int which = (b >= 6784);
        int base  = which ? 6784 : 6656;
        const float* src = Wsgc + (which ? (size_t)1024 * OUTF : 0);
        __half* dst = which ? g_WhC : g_WhA;
        int i = (b - base) * 256 + t;
        float4 v = ((const float4*)src)[i];
        __half2 lo = __floats2half2_rn(v.x, v.y);
        __half2 hi = __floats2half2_rn(v.z, v.w);
        uint2 packed;
        packed.x = *(unsigned*)&lo;
        packed.y = *(unsigned*)&hi;
        ((uint2*)dst)[i] = packed;
    }
}

// ---- block-redundant sum of 4096 floats (deterministic order) --------------
__device__ __forceinline__ float block_sum4096(const float* v, int t) {
    __shared__ float sred[8];
    __shared__ float sbc;
    float s = 0.f;
    const float4* v4 = (const float4*)v;
#pragma unroll
    for (int i = 0; i < 4; i++) {
        float4 a = v4[t + i * 256];
        s += (a.x + a.y) + (a.z + a.w);
    }
    for (int o = 16; o; o >>= 1) s += __shfl_xor_sync(0xffffffffu, s, o);
    if ((t & 31) == 0) sred[t >> 5] = s;
    __syncthreads();
    if (t < 32) {
        float r = (t < 8) ? sred[t] : 0.f;
        for (int o = 4; o; o >>= 1) r += __shfl_xor_sync(0xffffffffu, r, o);
        if (t == 0) sbc = r;
    }
    __syncthreads();
    return sbc;
}

// ---- SpMM: 4 independent 64-thr groups per 256-thr block, NO barrier -------
// Neighbor indices via broadcast __ldg (same addr across group -> L1 hit).
// mode 0: xh -> y1h ; mode 1: y1h -> y2h (ungated) ; mode 2: y2h -> y3h (!skip3)
__device__ __forceinline__ void spmm_g4(int mode, int blk) {
    const __half* __restrict__ src =
        (mode == 0) ? g_xh : ((mode == 1) ? g_y1h : g_y2h);
    __half* dst = (mode == 0) ? g_y1h : ((mode == 1) ? g_y2h : g_y3h);

    int g   = threadIdx.x >> 6;     // 0..3 row group
    int lt  = threadIdx.x & 63;
    int row = blk * 4 + g;

    if (mode == 2 && g_skip3[row]) return;
    int deg = g_deg[row];
    const int* __restrict__ nb = g_nbr + (size_t)row * MAXD;

    int c = lt << 3;                // 64 threads * 8 halves = 512 cols
    float acc[8];
#pragma unroll
    for (int i = 0; i < 8; i++) acc[i] = 0.f;

    int k = 0;
    for (; k + 8 <= deg; k += 8) {
        int j[8];
#pragma unroll
        for (int u = 0; u < 8; u++) j[u] = __ldg(nb + k + u);
        uint4 r[8];
#pragma unroll
        for (int u = 0; u < 8; u++)
            r[u] = *(const uint4*)(src + (size_t)j[u] * INF_ + c);
#pragma unroll
        for (int u = 0; u < 8; u++) {
            float2 f0 = __half22float2(*(__half2*)&r[u].x);
            float2 f1 = __half22float2(*(__half2*)&r[u].y);
            float2 f2 = __half22float2(*(__half2*)&r[u].z);
            float2 f3 = __half22float2(*(__half2*)&r[u].w);
            acc[0] += f0.x; acc[1] += f0.y; acc[2] += f1.x; acc[3] += f1.y;
            acc[4] += f2.x; acc[5] += f2.y; acc[6] += f3.x; acc[7] += f3.y;
        }
    }
    for (; k < deg; k++) {
        int j = __ldg(nb + k);
        uint4 rv = *(const uint4*)(src + (size_t)j * INF_ + c);
        float2 f0 = __half22float2(*(__half2*)&rv.x);
        float2 f1 = __half22float2(*(__half2*)&rv.y);
        float2 f2 = __half22float2(*(__half2*)&rv.z);
        float2 f3 = __half22float2(*(__half2*)&rv.w);
        acc[0] += f0.x; acc[1] += f0.y; acc[2] += f1.x; acc[3] += f1.y;
        acc[4] += f2.x; acc[5] += f2.y; acc[6] += f3.x; acc[7] += f3.y;
    }

    uint4 packed;
    __half2 h0 = __floats2half2_rn(acc[0], acc[1]);
    __half2 h1 = __floats2half2_rn(acc[2], acc[3]);
    __half2 h2 = __floats2half2_rn(acc[4], acc[5]);
    __half2 h3 = __floats2half2_rn(acc[6], acc[7]);
    packed.x = *(unsigned*)&h0; packed.y = *(unsigned*)&h1;
    packed.z = *(unsigned*)&h2; packed.w = *(unsigned*)&h3;
    *(uint4*)(dst + (size_t)row * INF_ + c) = packed;
}

// ---- gat1 body: h1=elu((adj@phu)/S1); h2=h1@W2; e2=exp(h2*a2[1]); qu=e2*h2 -
__device__ __forceinline__ void gat1_body(int blk, const float* __restrict__ W2,
                                          const float* __restrict__ a2) {
    int t    = threadIdx.x;
    float S1 = block_sum4096(g_e1, t);

    int lane = t & 31;
    int row  = blk * 8 + (t >> 5);
    int deg  = g_deg[row];
    const int* nb = g_nbr + (size_t)row * MAXD;

    float acc[HID];
#pragma unroll
    for (int f = 0; f < HID; f++) acc[f] = 0.f;

    for (int k = lane; k < deg; k += 32) {
        int j = nb[k];
        float4 A = *(const float4*)(g_phu + j * HID);
        float4 B = *(const float4*)(g_phu + j * HID + 4);
        acc[0] += A.x; acc[1] += A.y; acc[2] += A.z; acc[3] += A.w;
        acc[4] += B.x; acc[5] += B.y; acc[6] += B.z; acc[7] += B.w;
    }
#pragma unroll
    for (int f = 0; f < HID; f++)
        for (int o = 16; o; o >>= 1) acc[f] += __shfl_xor_sync(0xffffffffu, acc[f], o);

    if (lane == 0) {
        float invS = 1.f / S1;
        float h2 = 0.f;
#pragma unroll
        for (int f = 0; f < HID; f++) {
            float v = acc[f] * invS;
            v = v > 0.f ? v : (expf(v) - 1.f);   // elu
            h2 += v * W2[f];
        }
        float e2 = expf(h2 * a2[1]);
        g_e2[row] = e2;
        g_qu[row] = e2 * h2;
    }
}

// ---- mask body: s2=(adj@qu)/S2; elu; threshold; row lists; skip3 -----------
__device__ __forceinline__ void mask_body(int blk) {
    int t    = threadIdx.x;
    float S2 = block_sum4096(g_e2, t);

    int lane = t & 31;
    int row  = blk * 8 + (t >> 5);
    int deg  = g_deg[row];
    const int* nb = g_nbr + (size_t)row * MAXD;

    float s = 0.f;
    for (int k = lane; k < deg; k += 32) s += g_qu[nb[k]];
    for (int o = 16; o; o >>= 1) s += __shfl_xor_sync(0xffffffffu, s, o);

    if (lane == 0) {
        float s2 = s / S2;
        float sc = s2 > 0.f ? s2 : (expf(s2) - 1.f);   // elu
        int which = (sc > 0.7f) ? 0 : 1;
        g_skip3[row] = (which == 0);
        int pos = atomicAdd(&g_cnt[which], 1);
        g_rows[which][pos] = row;
    }
}

// ---- GEMM body via wmma (HMMA fp16 -> fp32 acc) ----------------------------
#define GLDA_S 72    // halves (64 + 8 pad)
#define GLDB_S 136   // halves (128 + 8 pad)
#define GLDS_F 132   // floats (128 + 4 pad)

__device__ __forceinline__ void gemm_body(int which, int bx, int by,
                                          const float* __restrict__ bias,
                                          float* __restrict__ out) {
    __shared__ __align__(16) char buf[64 * GLDS_F * 4];
    __shared__ int ridx[64];

    __half* sA = (__half*)buf;
    __half* sB = (__half*)(buf + 64 * GLDA_S * 2);
    float*  stage = (float*)buf;

    int cnt   = g_cnt[which];
    int rbase = bx * 64;
    if (rbase >= cnt) return;

    const __half* A = which ? g_y3h : g_y1h;
    const __half* W = which ? g_WhC : g_WhA;
    int cb = by * 128;

    int t = threadIdx.x;   // 256
    int warp = t >> 5;
    int wrow = warp & 3;
    int wcol = warp >> 2;

    if (t < 64) {
        int li = rbase + t;
        ridx[t] = (li < cnt) ? g_rows[which][li] : -1;
    }
    __syncthreads();

    int myArow0 = ridx[t >> 2];
    const __half* aSrc = A + (size_t)(myArow0 < 0 ? 0 : myArow0) * INF_;
    int apart = t & 3;

    wmma::fragment<wmma::accumulator, 16, 16, 16, float> cfr[4];
#pragma unroll
    for (int j = 0; j < 4; j++) wmma::fill_fragment(cfr[j], 0.f);

    for (int kc = 0; kc < INF_; kc += 64) {
#pragma unroll
        for (int u = 0; u < 2; u++) {
            int chunk = apart * 2 + u;
            uint4 v = *(const uint4*)(aSrc + kc + chunk * 8);
            *(uint4*)(sA + (t >> 2) * GLDA_S + chunk * 8) = v;
        }
#pragma unroll
        for (int v4 = 0; v4 < 4; v4++) {
            int idx = v4 * 256 + t;
            int krow = idx >> 4, chunk = idx & 15;
            uint4 v = *(const uint4*)(W + (size_t)(kc + krow) * OUTF + cb + chunk * 8);
            *(uint4*)(sB + krow * GLDB_S + chunk * 8) = v;
        }
        __syncthreads();

#pragma unroll
        for (int ks = 0; ks < 4; ks++) {
            wmma::fragment<wmma::matrix_a, 16, 16, 16, __half, wmma::row_major> afr;
            wmma::load_matrix_sync(afr, sA + wrow * 16 * GLDA_S + ks * 16, GLDA_S);
#pragma unroll
            for (int j = 0; j < 4; j++) {
                wmma::fragment<wmma::matrix_b, 16, 16, 16, __half, wmma::row_major> bfr;
                wmma::load_matrix_sync(bfr, sB + ks * 16 * GLDB_S + wcol * 64 + j * 16, GLDB_S);
                wmma::mma_sync(cfr[j], afr, bfr, cfr[j]);
            }
        }
        __syncthreads();
    }

#pragma unroll
    for (int j = 0; j < 4; j++)
        wmma::store_matrix_sync(stage + wrow * 16 * GLDS_F + wcol * 64 + j * 16,
                                cfr[j], GLDS_F, wmma::mem_row_major);
    __syncthreads();

#pragma unroll
    for (int w = 0; w < 8; w++) {
        int idx = w * 256 + t;
        int rl = idx >> 5, chunk = idx & 31;
        int col = chunk * 4;
        int grow = ridx[rl];
        if (grow >= 0) {
            float4 v = *(const float4*)(stage + rl * GLDS_F + col);
            float4 bv = *(const float4*)(bias + cb + col);
            v.x += bv.x; v.y += bv.y; v.z += bv.z; v.w += bv.w;
            *(float4*)(out + (size_t)grow * OUTF + cb + col) = v;
        }
    }
}

// ---- L2: spmm pass0 [0,1024) | gat1 [1024,1536) ----------------------------
__global__ void k_sp0_gat1(const float* __restrict__ W2, const float* __restrict__ a2) {
    if (blockIdx.x < 1024) spmm_g4(0, blockIdx.x);
    else                   gat1_body(blockIdx.x - 1024, W2, a2);
}

// ---- L3: spmm pass1 (ungated) [0,1024) | mask [1024,1536) ------------------
__global__ void k_sp1_mask() {
    if (blockIdx.x < 1024) spmm_g4(1, blockIdx.x);
    else                   mask_body(blockIdx.x - 1024);
}

// ---- L4: spmm pass2 (skip3-gated) [0,1024) | gemm which=0 [1024,1152) ------
__global__ void k_sp2_gemm0(const float* __restrict__ bias, float* __restrict__ out) {
    if (blockIdx.x < 1024) {
        spmm_g4(2, blockIdx.x);
    } else {
        int b = blockIdx.x - 1024;        // 0..127
        gemm_body(0, b & 63, b >> 6, bias, out);
    }
}

// ---- L5: gemm which=1 ------------------------------------------------------
__global__ void k_gemm1(const float* __restrict__ bias, float* __restrict__ out) {
    gemm_body(1, blockIdx.x, blockIdx.y, bias, out);
}

// ---------------- launcher --------------------------------------------------
extern "C" void kernel_launch(void* const* d_in, const int* in_sizes, int n_in,
                              void* d_out, int out_size) {
    const float* x    = (const float*)d_in[0];
    const float* adj  = (const float*)d_in[1];
    const float* W1   = (const float*)d_in[2];
    const float* a1   = (const float*)d_in[3];
    const float* W2   = (const float*)d_in[4];
    const float* a2   = (const float*)d_in[5];
    const float* Wsgc = (const float*)d_in[6];
    const float* bsgc = (const float*)d_in[7];
    float* out = (float*)d_out;

    k_prelude<<<6912, 256>>>(adj, x, W1, a1, Wsgc);
    k_sp0_gat1<<<1536, 256>>>(W2, a2);        // y1 = adj@x   || gat1
    k_sp1_mask<<<1536, 256>>>();              // y2 = adj^2@x || mask
    k_sp2_gemm0<<<1152, 256>>>(bsgc, out);    // y3 = adj^3@x || gemm(mask==1)
    k_gemm1<<<dim3(64, 2), 256>>>(bsgc, out); // gemm(mask==0)
}

// round 8
// speedup vs baseline: 2.5016x; 1.0382x over previous
#include <cuda_runtime.h>
#include <cuda_fp16.h>
#include <mma.h>
#include <math.h>

using namespace nvcuda;

#define NN    4096
#define INF_  512
#define HID   8
#define OUTF  256
#define MAXD  128

// ---------------- scratch (static device globals) ---------------------------
__device__ int    g_deg[NN];
__device__ int    g_nbr[NN * MAXD];
__device__ float  g_phu[NN * HID];    // exp(dst1[j]) * h[j]   (unnormalized)
__device__ float  g_e1[NN];           // exp(dst1[j])
__device__ float  g_qu[NN];           // exp(d2[j]) * h2v[j]   (unnormalized)
__device__ float  g_e2[NN];           // exp(d2[j])
__device__ int    g_rows[2][NN];      // [0]=mask==1 (y1,Wa), [1]=mask==0 (y3,Wc)
__device__ int    g_cnt[2];
__device__ int    g_skip3[NN];        // 1 -> y3[row] never read
__device__ __half g_xh [NN * INF_];   // x in fp16
__device__ __half g_y1h[NN * INF_];   // adj   @ x
__device__ __half g_y2h[NN * INF_];   // adj^2 @ x
__device__ __half g_y3h[NN * INF_];   // adj^3 @ x
__device__ __half g_WhA[INF_ * OUTF]; // W_sgc[0:512]     in fp16
__device__ __half g_WhC[INF_ * OUTF]; // W_sgc[1024:1536] in fp16

// ---- fused prelude: build nbr lists | x->fp16 | h=x@W1 chain | W->fp16 -----
__global__ void k_prelude(const float* __restrict__ adj, const float* __restrict__ x,
                          const float* __restrict__ W1, const float* __restrict__ a1,
                          const float* __restrict__ Wsgc) {
    int b = blockIdx.x;
    int t = threadIdx.x;          // 256

    if (b < 4096) {
        int row = b;
        const float4* ar = (const float4*)(adj + (size_t)row * NN);
        float4 v[4];
        int cnt = 0;
#pragma unroll
        for (int i = 0; i < 4; i++) {
            v[i] = ar[t + i * 256];
            cnt += (v[i].x != 0.f) + (v[i].y != 0.f) + (v[i].z != 0.f) + (v[i].w != 0.f);
        }
        __shared__ int sc[256];
        sc[t] = cnt;
        __syncthreads();
        for (int d = 1; d < 256; d <<= 1) {
            int val = (t >= d) ? sc[t - d] : 0;
            __syncthreads();
            if (t >= d) sc[t] += val;
            __syncthreads();
        }
        int pos   = sc[t] - cnt;
        int total = sc[255];
        int* nb = g_nbr + (size_t)row * MAXD;
#pragma unroll
        for (int i = 0; i < 4; i++) {
            int base = (t + i * 256) * 4;
            if (v[i].x != 0.f) { if (pos < MAXD) nb[pos] = base + 0; pos++; }
            if (v[i].y != 0.f) { if (pos < MAXD) nb[pos] = base + 1; pos++; }
            if (v[i].z != 0.f) { if (pos < MAXD) nb[pos] = base + 2; pos++; }
            if (v[i].w != 0.f) { if (pos < MAXD) nb[pos] = base + 3; pos++; }
        }
        if (t == 0) g_deg[row] = total < MAXD ? total : MAXD;
        if (row == 0 && t < 2) g_cnt[t] = 0;
    } else if (b < 6144) {
        int i = (b - 4096) * 256 + t;
        float4 v = ((const float4*)x)[i];
        __half2 lo = __floats2half2_rn(v.x, v.y);
        __half2 hi = __floats2half2_rn(v.z, v.w);
        uint2 packed;
        packed.x = *(unsigned*)&lo;
        packed.y = *(unsigned*)&hi;
        ((uint2*)g_xh)[i] = packed;
    } else if (b < 6656) {
        int lane = t & 31;
        int row  = (b - 6144) * 8 + (t >> 5);
        const float* xr = x + (size_t)row * INF_;
        float acc[HID];
#pragma unroll
        for (int f = 0; f < HID; f++) acc[f] = 0.f;
        for (int k = lane; k < INF_; k += 32) {
            float xv = xr[k];
            float4 wA = *(const float4*)(W1 + k * HID);
            float4 wB = *(const float4*)(W1 + k * HID + 4);
            acc[0] += xv * wA.x; acc[1] += xv * wA.y; acc[2] += xv * wA.z; acc[3] += xv * wA.w;
            acc[4] += xv * wB.x; acc[5] += xv * wB.y; acc[6] += xv * wB.z; acc[7] += xv * wB.w;
        }
#pragma unroll
        for (int f = 0; f < HID; f++)
            for (int o = 16; o; o >>= 1) acc[f] += __shfl_xor_sync(0xffffffffu, acc[f], o);
        if (lane == 0) {
            float d = 0.f;
#pragma unroll
            for (int f = 0; f < HID; f++) d += acc[f] * a1[HID + f];
            float e1 = expf(d);
            g_e1[row] = e1;
#pragma unroll
            for (int f = 0; f < HID; f++) g_phu[row * HID + f] = e1 * acc[f];
        }
    } else {
        int which = (b >= 6784);
        int base  = which ? 6784 : 6656;
        const float* src = Wsgc + (which ? (size_t)1024 * OUTF : 0);
        __half* dst = which ? g_WhC : g_WhA;
        int i = (b - base) * 256 + t;
        float4 v = ((const float4*)src)[i];
        __half2 lo = __floats2half2_rn(v.x, v.y);
        __half2 hi = __floats2half2_rn(v.z, v.w);
        uint2 packed;
        packed.x = *(unsigned*)&lo;
        packed.y = *(unsigned*)&hi;
        ((uint2*)dst)[i] = packed;
    }
}

// ---- block-redundant sum of 4096 floats (deterministic order) --------------
__device__ __forceinline__ float block_sum4096(const float* v, int t) {
    __shared__ float sred[8];
    __shared__ float sbc;
    float s = 0.f;
    const float4* v4 = (const float4*)v;
#pragma unroll
    for (int i = 0; i < 4; i++) {
        float4 a = v4[t + i * 256];
        s += (a.x + a.y) + (a.z + a.w);
    }
    for (int o = 16; o; o >>= 1) s += __shfl_xor_sync(0xffffffffu, s, o);
    if ((t & 31) == 0) sred[t >> 5] = s;
    __syncthreads();
    if (t < 32) {
        float r = (t < 8) ? sred[t] : 0.f;
        for (int o = 4; o; o >>= 1) r += __shfl_xor_sync(0xffffffffu, r, o);
        if (t == 0) sbc = r;
    }
    __syncthreads();
    return sbc;
}

// ---- SpMM: 4 independent 64-thr groups per 256-thr block, NO barrier -------
// mode 0: xh -> y1h ; mode 1: y1h -> y2h ; mode 2: y2h -> y3h (!skip3)
__device__ __forceinline__ void spmm_g4(int mode, int blk) {
    const __half* __restrict__ src =
        (mode == 0) ? g_xh : ((mode == 1) ? g_y1h : g_y2h);
    __half* dst = (mode == 0) ? g_y1h : ((mode == 1) ? g_y2h : g_y3h);

    int g   = threadIdx.x >> 6;     // 0..3 row group
    int lt  = threadIdx.x & 63;
    int row = blk * 4 + g;

    if (mode == 2 && g_skip3[row]) return;
    int deg = g_deg[row];
    const int* __restrict__ nb = g_nbr + (size_t)row * MAXD;

    int c = lt << 3;                // 64 threads * 8 halves = 512 cols
    float acc[8];
#pragma unroll
    for (int i = 0; i < 8; i++) acc[i] = 0.f;

    int k = 0;
    for (; k + 8 <= deg; k += 8) {
        int j[8];
#pragma unroll
        for (int u = 0; u < 8; u++) j[u] = __ldg(nb + k + u);
        uint4 r[8];
#pragma unroll
        for (int u = 0; u < 8; u++)
            r[u] = *(const uint4*)(src + (size_t)j[u] * INF_ + c);
#pragma unroll
        for (int u = 0; u < 8; u++) {
            float2 f0 = __half22float2(*(__half2*)&r[u].x);
            float2 f1 = __half22float2(*(__half2*)&r[u].y);
            float2 f2 = __half22float2(*(__half2*)&r[u].z);
            float2 f3 = __half22float2(*(__half2*)&r[u].w);
            acc[0] += f0.x; acc[1] += f0.y; acc[2] += f1.x; acc[3] += f1.y;
            acc[4] += f2.x; acc[5] += f2.y; acc[6] += f3.x; acc[7] += f3.y;
        }
    }
    for (; k < deg; k++) {
        int j = __ldg(nb + k);
        uint4 rv = *(const uint4*)(src + (size_t)j * INF_ + c);
        float2 f0 = __half22float2(*(__half2*)&rv.x);
        float2 f1 = __half22float2(*(__half2*)&rv.y);
        float2 f2 = __half22float2(*(__half2*)&rv.z);
        float2 f3 = __half22float2(*(__half2*)&rv.w);
        acc[0] += f0.x; acc[1] += f0.y; acc[2] += f1.x; acc[3] += f1.y;
        acc[4] += f2.x; acc[5] += f2.y; acc[6] += f3.x; acc[7] += f3.y;
    }

    uint4 packed;
    __half2 h0 = __floats2half2_rn(acc[0], acc[1]);
    __half2 h1 = __floats2half2_rn(acc[2], acc[3]);
    __half2 h2 = __floats2half2_rn(acc[4], acc[5]);
    __half2 h3 = __floats2half2_rn(acc[6], acc[7]);
    packed.x = *(unsigned*)&h0; packed.y = *(unsigned*)&h1;
    packed.z = *(unsigned*)&h2; packed.w = *(unsigned*)&h3;
    *(uint4*)(dst + (size_t)row * INF_ + c) = packed;
}

// ---- gat1 body: h1=elu((adj@phu)/S1); h2=h1@W2; e2=exp(h2*a2[1]); qu=e2*h2 -
__device__ __forceinline__ void gat1_body(int blk, const float* __restrict__ W2,
                                          const float* __restrict__ a2) {
    int t    = threadIdx.x;
    float S1 = block_sum4096(g_e1, t);

    int lane = t & 31;
    int row  = blk * 8 + (t >> 5);
    int deg  = g_deg[row];
    const int* nb = g_nbr + (size_t)row * MAXD;

    float acc[HID];
#pragma unroll
    for (int f = 0; f < HID; f++) acc[f] = 0.f;

    for (int k = lane; k < deg; k += 32) {
        int j = nb[k];
        float4 A = *(const float4*)(g_phu + j * HID);
        float4 B = *(const float4*)(g_phu + j * HID + 4);
        acc[0] += A.x; acc[1] += A.y; acc[2] += A.z; acc[3] += A.w;
        acc[4] += B.x; acc[5] += B.y; acc[6] += B.z; acc[7] += B.w;
    }
#pragma unroll
    for (int f = 0; f < HID; f++)
        for (int o = 16; o; o >>= 1) acc[f] += __shfl_xor_sync(0xffffffffu, acc[f], o);

    if (lane == 0) {
        float invS = 1.f / S1;
        float h2 = 0.f;
#pragma unroll
        for (int f = 0; f < HID; f++) {
            float v = acc[f] * invS;
            v = v > 0.f ? v : (expf(v) - 1.f);   // elu
            h2 += v * W2[f];
        }
        float e2 = expf(h2 * a2[1]);
        g_e2[row] = e2;
        g_qu[row] = e2 * h2;
    }
}

// ---- mask body: s2=(adj@qu)/S2; elu; threshold; row lists; skip3 -----------
__device__ __forceinline__ void mask_body(int blk) {
    int t    = threadIdx.x;
    float S2 = block_sum4096(g_e2, t);

    int lane = t & 31;
    int row  = blk * 8 + (t >> 5);
    int deg  = g_deg[row];
    const int* nb = g_nbr + (size_t)row * MAXD;

    float s = 0.f;
    for (int k = lane; k < deg; k += 32) s += g_qu[nb[k]];
    for (int o = 16; o; o >>= 1) s += __shfl_xor_sync(0xffffffffu, s, o);

    if (lane == 0) {
        float s2 = s / S2;
        float sc = s2 > 0.f ? s2 : (expf(s2) - 1.f);   // elu
        int which = (sc > 0.7f) ? 0 : 1;
        g_skip3[row] = (which == 0);
        int pos = atomicAdd(&g_cnt[which], 1);
        g_rows[which][pos] = row;
    }
}

// ---- L2: spmm pass0 [0,1024) | gat1 [1024,1536) ----------------------------
__global__ void __launch_bounds__(256, 6)
k_sp0_gat1(const float* __restrict__ W2, const float* __restrict__ a2) {
    if (blockIdx.x < 1024) spmm_g4(0, blockIdx.x);
    else                   gat1_body(blockIdx.x - 1024, W2, a2);
}

// ---- L3: spmm pass1 [0,1024) | mask [1024,1536) ----------------------------
__global__ void __launch_bounds__(256, 6)
k_sp1_mask() {
    if (blockIdx.x < 1024) spmm_g4(1, blockIdx.x);
    else                   mask_body(blockIdx.x - 1024);
}

// ---- L4: spmm pass2 standalone (skip3-gated) -------------------------------
__global__ void __launch_bounds__(256, 6)
k_spmm2() {
    spmm_g4(2, blockIdx.x);
}

// ---- L5: GEMM both halves via wmma (HMMA fp16 -> fp32 acc) -----------------
#define GLDA_S 72    // halves (64 + 8 pad)
#define GLDB_S 136   // halves (128 + 8 pad)
#define GLDS_F 132   // floats (128 + 4 pad)

__global__ void k_gemm(const float* __restrict__ bias, float* __restrict__ out) {
    __shared__ __align__(16) char buf[64 * GLDS_F * 4];
    __shared__ int ridx[64];

    __half* sA = (__half*)buf;
    __half* sB = (__half*)(buf + 64 * GLDA_S * 2);
    float*  stage = (float*)buf;

    int which = blockIdx.z;
    int cnt   = g_cnt[which];
    int rbase = blockIdx.x * 64;
    if (rbase >= cnt) return;

    const __half* A = which ? g_y3h : g_y1h;
    const __half* W = which ? g_WhC : g_WhA;
    int cb = blockIdx.y * 128;

    int t = threadIdx.x;   // 256
    int warp = t >> 5;
    int wrow = warp & 3;
    int wcol = warp >> 2;

    if (t < 64) {
        int li = rbase + t;
        ridx[t] = (li < cnt) ? g_rows[which][li] : -1;
    }
    __syncthreads();

    int myArow0 = ridx[t >> 2];
    const __half* aSrc = A + (size_t)(myArow0 < 0 ? 0 : myArow0) * INF_;
    int apart = t & 3;

    wmma::fragment<wmma::accumulator, 16, 16, 16, float> cfr[4];
#pragma unroll
    for (int j = 0; j < 4; j++) wmma::fill_fragment(cfr[j], 0.f);

    for (int kc = 0; kc < INF_; kc += 64) {
#pragma unroll
        for (int u = 0; u < 2; u++) {
            int chunk = apart * 2 + u;
            uint4 v = *(const uint4*)(aSrc + kc + chunk * 8);
            *(uint4*)(sA + (t >> 2) * GLDA_S + chunk * 8) = v;
        }
#pragma unroll
        for (int v4 = 0; v4 < 4; v4++) {
            int idx = v4 * 256 + t;
            int krow = idx >> 4, chunk = idx & 15;
            uint4 v = *(const uint4*)(W + (size_t)(kc + krow) * OUTF + cb + chunk * 8);
            *(uint4*)(sB + krow * GLDB_S + chunk * 8) = v;
        }
        __syncthreads();

#pragma unroll
        for (int ks = 0; ks < 4; ks++) {
            wmma::fragment<wmma::matrix_a, 16, 16, 16, __half, wmma::row_major> afr;
            wmma::load_matrix_sync(afr, sA + wrow * 16 * GLDA_S + ks * 16, GLDA_S);
#pragma unroll
            for (int j = 0; j < 4; j++) {
                wmma::fragment<wmma::matrix_b, 16, 16, 16, __half, wmma::row_major> bfr;
                wmma::load_matrix_sync(bfr, sB + ks * 16 * GLDB_S + wcol * 64 + j * 16, GLDB_S);
                wmma::mma_sync(cfr[j], afr, bfr, cfr[j]);
            }
        }
        __syncthreads();
    }

#pragma unroll
    for (int j = 0; j < 4; j++)
        wmma::store_matrix_sync(stage + wrow * 16 * GLDS_F + wcol * 64 + j * 16,
                                cfr[j], GLDS_F, wmma::mem_row_major);
    __syncthreads();

#pragma unroll
    for (int w = 0; w < 8; w++) {
        int idx = w * 256 + t;
        int rl = idx >> 5, chunk = idx & 31;
        int col = chunk * 4;
        int grow = ridx[rl];
        if (grow >= 0) {
            float4 v = *(const float4*)(stage + rl * GLDS_F + col);
            float4 bv = *(const float4*)(bias + cb + col);
            v.x += bv.x; v.y += bv.y; v.z += bv.z; v.w += bv.w;
            *(float4*)(out + (size_t)grow * OUTF + cb + col) = v;
        }
    }
}

// ---------------- launcher --------------------------------------------------
extern "C" void kernel_launch(void* const* d_in, const int* in_sizes, int n_in,
                              void* d_out, int out_size) {
    const float* x    = (const float*)d_in[0];
    const float* adj  = (const float*)d_in[1];
    const float* W1   = (const float*)d_in[2];
    const float* a1   = (const float*)d_in[3];
    const float* W2   = (const float*)d_in[4];
    const float* a2   = (const float*)d_in[5];
    const float* Wsgc = (const float*)d_in[6];
    const float* bsgc = (const float*)d_in[7];
    float* out = (float*)d_out;

    k_prelude<<<6912, 256>>>(adj, x, W1, a1, Wsgc);
    k_sp0_gat1<<<1536, 256>>>(W2, a2);            // y1 = adj@x   || gat1
    k_sp1_mask<<<1536, 256>>>();                  // y2 = adj^2@x || mask
    k_spmm2<<<1024, 256>>>();                     // y3 = adj^3@x (skip3-gated)
    k_gemm<<<dim3(64, 2, 2), 256>>>(bsgc, out);   // both routed halves
}

// round 9
// speedup vs baseline: 2.8060x; 1.1217x over previous
#include <cuda_runtime.h>
#include <cuda_fp16.h>
#include <mma.h>
#include <math.h>

using namespace nvcuda;

#define NN    4096
#define INF_  512
#define HID   8
#define OUTF  256
#define MAXD  128

// ---------------- scratch (static device globals) ---------------------------
__device__ int    g_deg[NN];
__device__ int    g_nbr[NN * MAXD];
__device__ float  g_phu[NN * HID];    // exp(dst1[j]) * h[j]   (unnormalized)
__device__ float  g_e1[NN];           // exp(dst1[j])
__device__ float  g_qu[NN];           // exp(d2[j]) * h2v[j]   (unnormalized)
__device__ float  g_e2[NN];           // exp(d2[j])
__device__ int    g_mask1[NN];        // 1 -> row uses A@v (W_A path)
__device__ __half g_xh[NN * INF_];    // x in fp16
__device__ __half g_v [NN * OUTF];    // x @ W_A   (for mask==1 rows)
__device__ __half g_u [NN * OUTF];    // x @ W_C   (for mask==0 rows)
__device__ __half g_z1[NN * OUTF];    // A @ u
__device__ __half g_z2[NN * OUTF];    // A^2 @ u
__device__ __half g_WhA[INF_ * OUTF]; // W_sgc[0:512]     in fp16
__device__ __half g_WhC[INF_ * OUTF]; // W_sgc[1024:1536] in fp16

// ---- fused prelude: build nbr lists | x->fp16 | h=x@W1 chain | W->fp16 -----
__global__ void k_prelude(const float* __restrict__ adj, const float* __restrict__ x,
                          const float* __restrict__ W1, const float* __restrict__ a1,
                          const float* __restrict__ Wsgc) {
    int b = blockIdx.x;
    int t = threadIdx.x;          // 256

    if (b < 4096) {
        int row = b;
        const float4* ar = (const float4*)(adj + (size_t)row * NN);
        float4 v[4];
        int cnt = 0;
#pragma unroll
        for (int i = 0; i < 4; i++) {
            v[i] = ar[t + i * 256];
            cnt += (v[i].x != 0.f) + (v[i].y != 0.f) + (v[i].z != 0.f) + (v[i].w != 0.f);
        }
        __shared__ int sc[256];
        sc[t] = cnt;
        __syncthreads();
        for (int d = 1; d < 256; d <<= 1) {
            int val = (t >= d) ? sc[t - d] : 0;
            __syncthreads();
            if (t >= d) sc[t] += val;
            __syncthreads();
        }
        int pos   = sc[t] - cnt;
        int total = sc[255];
        int* nb = g_nbr + (size_t)row * MAXD;
#pragma unroll
        for (int i = 0; i < 4; i++) {
            int base = (t + i * 256) * 4;
            if (v[i].x != 0.f) { if (pos < MAXD) nb[pos] = base + 0; pos++; }
            if (v[i].y != 0.f) { if (pos < MAXD) nb[pos] = base + 1; pos++; }
            if (v[i].z != 0.f) { if (pos < MAXD) nb[pos] = base + 2; pos++; }
            if (v[i].w != 0.f) { if (pos < MAXD) nb[pos] = base + 3; pos++; }
        }
        if (t == 0) g_deg[row] = total < MAXD ? total : MAXD;
    } else if (b < 6144) {
        int i = (b - 4096) * 256 + t;
        float4 v = ((const float4*)x)[i];
        __half2 lo = __floats2half2_rn(v.x, v.y);
        __half2 hi = __floats2half2_rn(v.z, v.w);
        uint2 packed;
        packed.x = *(unsigned*)&lo;
        packed.y = *(unsigned*)&hi;
        ((uint2*)g_xh)[i] = packed;
    } else if (b < 6656) {
        int lane = t & 31;
        int row  = (b - 6144) * 8 + (t >> 5);
        const float* xr = x + (size_t)row * INF_;
        float acc[HID];
#pragma unroll
        for (int f = 0; f < HID; f++) acc[f] = 0.f;
        for (int k = lane; k < INF_; k += 32) {
            float xv = xr[k];
            float4 wA = *(const float4*)(W1 + k * HID);
            float4 wB = *(const float4*)(W1 + k * HID + 4);
            acc[0] += xv * wA.x; acc[1] += xv * wA.y; acc[2] += xv * wA.z; acc[3] += xv * wA.w;
            acc[4] += xv * wB.x; acc[5] += xv * wB.y; acc[6] += xv * wB.z; acc[7] += xv * wB.w;
        }
#pragma unroll
        for (int f = 0; f < HID; f++)
            for (int o = 16; o; o >>= 1) acc[f] += __shfl_xor_sync(0xffffffffu, acc[f], o);
        if (lane == 0) {
            float d = 0.f;
#pragma unroll
            for (int f = 0; f < HID; f++) d += acc[f] * a1[HID + f];
            float e1 = expf(d);
            g_e1[row] = e1;
#pragma unroll
            for (int f = 0; f < HID; f++) g_phu[row * HID + f] = e1 * acc[f];
        }
    } else {
        int which = (b >= 6784);
        int base  = which ? 6784 : 6656;
        const float* src = Wsgc + (which ? (size_t)1024 * OUTF : 0);
        __half* dst = which ? g_WhC : g_WhA;
        int i = (b - base) * 256 + t;
        float4 v = ((const float4*)src)[i];
        __half2 lo = __floats2half2_rn(v.x, v.y);
        __half2 hi = __floats2half2_rn(v.z, v.w);
        uint2 packed;
        packed.x = *(unsigned*)&lo;
        packed.y = *(unsigned*)&hi;
        ((uint2*)dst)[i] = packed;
    }
}

// ---- block-redundant sum of 4096 floats (deterministic order) --------------
__device__ __forceinline__ float block_sum4096(const float* v, int t) {
    __shared__ float sred[8];
    __shared__ float sbc;
    float s = 0.f;
    const float4* v4 = (const float4*)v;
#pragma unroll
    for (int i = 0; i < 4; i++) {
        float4 a = v4[t + i * 256];
        s += (a.x + a.y) + (a.z + a.w);
    }
    for (int o = 16; o; o >>= 1) s += __shfl_xor_sync(0xffffffffu, s, o);
    if ((t & 31) == 0) sred[t >> 5] = s;
    __syncthreads();
    if (t < 32) {
        float r = (t < 8) ? sred[t] : 0.f;
        for (int o = 4; o; o >>= 1) r += __shfl_xor_sync(0xffffffffu, r, o);
        if (t == 0) sbc = r;
    }
    __syncthreads();
    return sbc;
}

// ---- gat1 body: h1=elu((adj@phu)/S1); h2=h1@W2; e2=exp(h2*a2[1]); qu=e2*h2 -
__device__ __forceinline__ void gat1_body(int blk, const float* __restrict__ W2,
                                          const float* __restrict__ a2) {
    int t    = threadIdx.x;
    float S1 = block_sum4096(g_e1, t);

    int lane = t & 31;
    int row  = blk * 8 + (t >> 5);
    int deg  = g_deg[row];
    const int* nb = g_nbr + (size_t)row * MAXD;

    float acc[HID];
#pragma unroll
    for (int f = 0; f < HID; f++) acc[f] = 0.f;

    for (int k = lane; k < deg; k += 32) {
        int j = nb[k];
        float4 A = *(const float4*)(g_phu + j * HID);
        float4 B = *(const float4*)(g_phu + j * HID + 4);
        acc[0] += A.x; acc[1] += A.y; acc[2] += A.z; acc[3] += A.w;
        acc[4] += B.x; acc[5] += B.y; acc[6] += B.z; acc[7] += B.w;
    }
#pragma unroll
    for (int f = 0; f < HID; f++)
        for (int o = 16; o; o >>= 1) acc[f] += __shfl_xor_sync(0xffffffffu, acc[f], o);

    if (lane == 0) {
        float invS = 1.f / S1;
        float h2 = 0.f;
#pragma unroll
        for (int f = 0; f < HID; f++) {
            float v = acc[f] * invS;
            v = v > 0.f ? v : (expf(v) - 1.f);   // elu
            h2 += v * W2[f];
        }
        float e2 = expf(h2 * a2[1]);
        g_e2[row] = e2;
        g_qu[row] = e2 * h2;
    }
}

// ---- mask body: s2=(adj@qu)/S2; elu; threshold -> g_mask1 ------------------
__device__ __forceinline__ void mask_body(int blk) {
    int t    = threadIdx.x;
    float S2 = block_sum4096(g_e2, t);

    int lane = t & 31;
    int row  = blk * 8 + (t >> 5);
    int deg  = g_deg[row];
    const int* nb = g_nbr + (size_t)row * MAXD;

    float s = 0.f;
    for (int k = lane; k < deg; k += 32) s += g_qu[nb[k]];
    for (int o = 16; o; o >>= 1) s += __shfl_xor_sync(0xffffffffu, s, o);

    if (lane == 0) {
        float s2 = s / S2;
        float sc = s2 > 0.f ? s2 : (expf(s2) - 1.f);   // elu
        g_mask1[row] = (sc > 0.7f) ? 1 : 0;
    }
}

// ---- dense GEMM body: dst[4096x256] = xh @ Wh (fp16 out, fp32 acc) ---------
#define GLDA_S 72    // halves (64 + 8 pad)
#define GLDB_S 136   // halves (128 + 8 pad)
#define GLDS_F 132   // floats (128 + 4 pad)

__device__ __forceinline__ void gemm_dense(int which, int bx, int by) {
    __shared__ __align__(16) char buf[64 * GLDS_F * 4];

    __half* sA = (__half*)buf;
    __half* sB = (__half*)(buf + 64 * GLDA_S * 2);
    float*  stage = (float*)buf;

    const __half* W   = which ? g_WhC : g_WhA;
    __half*       dst = which ? g_u   : g_v;
    int rbase = bx * 64;
    int cb    = by * 128;

    int t = threadIdx.x;   // 256
    int warp = t >> 5;
    int wrow = warp & 3;
    int wcol = warp >> 2;

    const __half* aSrc = g_xh + (size_t)(rbase + (t >> 2)) * INF_;
    int apart = t & 3;

    wmma::fragment<wmma::accumulator, 16, 16, 16, float> cfr[4];
#pragma unroll
    for (int j = 0; j < 4; j++) wmma::fill_fragment(cfr[j], 0.f);

    for (int kc = 0; kc < INF_; kc += 64) {
#pragma unroll
        for (int u = 0; u < 2; u++) {
            int chunk = apart * 2 + u;
            uint4 v = *(const uint4*)(aSrc + kc + chunk * 8);
            *(uint4*)(sA + (t >> 2) * GLDA_S + chunk * 8) = v;
        }
#pragma unroll
        for (int v4 = 0; v4 < 4; v4++) {
            int idx = v4 * 256 + t;
            int krow = idx >> 4, chunk = idx & 15;
            uint4 v = *(const uint4*)(W + (size_t)(kc + krow) * OUTF + cb + chunk * 8);
            *(uint4*)(sB + krow * GLDB_S + chunk * 8) = v;
        }
        __syncthreads();

#pragma unroll
        for (int ks = 0; ks < 4; ks++) {
            wmma::fragment<wmma::matrix_a, 16, 16, 16, __half, wmma::row_major> afr;
            wmma::load_matrix_sync(afr, sA + wrow * 16 * GLDA_S + ks * 16, GLDA_S);
#pragma unroll
            for (int j = 0; j < 4; j++) {
                wmma::fragment<wmma::matrix_b, 16, 16, 16, __half, wmma::row_major> bfr;
                wmma::load_matrix_sync(bfr, sB + ks * 16 * GLDB_S + wcol * 64 + j * 16, GLDB_S);
                wmma::mma_sync(cfr[j], afr, bfr, cfr[j]);
            }
        }
        __syncthreads();
    }

#pragma unroll
    for (int j = 0; j < 4; j++)
        wmma::store_matrix_sync(stage + wrow * 16 * GLDS_F + wcol * 64 + j * 16,
                                cfr[j], GLDS_F, wmma::mem_row_major);
    __syncthreads();

    // fp16 store: 64 rows x 128 cols -> dst
#pragma unroll
    for (int w = 0; w < 8; w++) {
        int idx = w * 256 + t;            // 0..2047, 4 cols each
        int rl = idx >> 5, chunk = idx & 31;
        int col = chunk * 4;
        float4 v = *(const float4*)(stage + rl * GLDS_F + col);
        __half2 h0 = __floats2half2_rn(v.x, v.y);
        __half2 h1 = __floats2half2_rn(v.z, v.w);
        uint2 p;
        p.x = *(unsigned*)&h0;
        p.y = *(unsigned*)&h1;
        *(uint2*)(dst + (size_t)(rbase + rl) * OUTF + cb + col) = p;
    }
}

// ---- SpMM 256-col: 8 warps/block, warp per row, 16B/thread -----------------
__device__ __forceinline__ void spmm256(const __half* __restrict__ src,
                                        __half* __restrict__ dst, int blk) {
    int wid  = threadIdx.x >> 5;
    int lane = threadIdx.x & 31;
    int row  = blk * 8 + wid;
    int deg  = g_deg[row];
    const int* __restrict__ nb = g_nbr + (size_t)row * MAXD;

    int c = lane << 3;               // 32 thr * 8 halves = 256 cols
    float acc[8];
#pragma unroll
    for (int i = 0; i < 8; i++) acc[i] = 0.f;

    int k = 0;
    for (; k + 8 <= deg; k += 8) {
        int j[8];
#pragma unroll
        for (int u = 0; u < 8; u++) j[u] = __ldg(nb + k + u);
        uint4 r[8];
#pragma unroll
        for (int u = 0; u < 8; u++)
            r[u] = *(const uint4*)(src + (size_t)j[u] * OUTF + c);
#pragma unroll
        for (int u = 0; u < 8; u++) {
            float2 f0 = __half22float2(*(__half2*)&r[u].x);
            float2 f1 = __half22float2(*(__half2*)&r[u].y);
            float2 f2 = __half22float2(*(__half2*)&r[u].z);
            float2 f3 = __half22float2(*(__half2*)&r[u].w);
            acc[0] += f0.x; acc[1] += f0.y; acc[2] += f1.x; acc[3] += f1.y;
            acc[4] += f2.x; acc[5] += f2.y; acc[6] += f3.x; acc[7] += f3.y;
        }
    }
    for (; k < deg; k++) {
        int j = __ldg(nb + k);
        uint4 rv = *(const uint4*)(src + (size_t)j * OUTF + c);
        float2 f0 = __half22float2(*(__half2*)&rv.x);
        float2 f1 = __half22float2(*(__half2*)&rv.y);
        float2 f2 = __half22float2(*(__half2*)&rv.z);
        float2 f3 = __half22float2(*(__half2*)&rv.w);
        acc[0] += f0.x; acc[1] += f0.y; acc[2] += f1.x; acc[3] += f1.y;
        acc[4] += f2.x; acc[5] += f2.y; acc[6] += f3.x; acc[7] += f3.y;
    }

    uint4 packed;
    __half2 h0 = __floats2half2_rn(acc[0], acc[1]);
    __half2 h1 = __floats2half2_rn(acc[2], acc[3]);
    __half2 h2 = __floats2half2_rn(acc[4], acc[5]);
    __half2 h3 = __floats2half2_rn(acc[6], acc[7]);
    packed.x = *(unsigned*)&h0; packed.y = *(unsigned*)&h1;
    packed.z = *(unsigned*)&h2; packed.w = *(unsigned*)&h3;
    *(uint4*)(dst + (size_t)row * OUTF + c) = packed;
}

// ---- L2: dense GEMMs u,v [0,256) | gat1 [256,768) --------------------------
__global__ void k_gemm_gat1(const float* __restrict__ W2, const float* __restrict__ a2) {
    int b = blockIdx.x;
    if (b < 256) {
        int which = b >> 7;            // 0: v=x@WA, 1: u=x@WC
        int tile  = b & 127;
        gemm_dense(which, tile >> 1, tile & 1);
    } else {
        gat1_body(b - 256, W2, a2);
    }
}

// ---- L3: z1 = A@u [0,512) | mask [512,1024) --------------------------------
__global__ void k_z1_mask() {
    int b = blockIdx.x;
    if (b < 512) spmm256(g_u, g_z1, b);
    else         mask_body(b - 512);
}

// ---- L4: z2 = A@z1 ----------------------------------------------------------
__global__ void k_z2() {
    spmm256(g_z1, g_z2, blockIdx.x);
}

// ---- L5: out[r] = (mask1 ? A@v : A@z2)[r] + bias (fp32) --------------------
__global__ void k_out(const float* __restrict__ bias, float* __restrict__ out) {
    int wid  = threadIdx.x >> 5;
    int lane = threadIdx.x & 31;
    int row  = blockIdx.x * 8 + wid;
    int deg  = g_deg[row];
    const int* __restrict__ nb = g_nbr + (size_t)row * MAXD;
    const __half* __restrict__ src = g_mask1[row] ? g_v : g_z2;

    int c = lane << 3;
    float acc[8];
#pragma unroll
    for (int i = 0; i < 8; i++) acc[i] = 0.f;

    int k = 0;
    for (; k + 8 <= deg; k += 8) {
        int j[8];
#pragma unroll
        for (int u = 0; u < 8; u++) j[u] = __ldg(nb + k + u);
        uint4 r[8];
#pragma unroll
        for (int u = 0; u < 8; u++)
            r[u] = *(const uint4*)(src + (size_t)j[u] * OUTF + c);
#pragma unroll
        for (int u = 0; u < 8; u++) {
            float2 f0 = __half22float2(*(__half2*)&r[u].x);
            float2 f1 = __half22float2(*(__half2*)&r[u].y);
            float2 f2 = __half22float2(*(__half2*)&r[u].z);
            float2 f3 = __half22float2(*(__half2*)&r[u].w);
            acc[0] += f0.x; acc[1] += f0.y; acc[2] += f1.x; acc[3] += f1.y;
            acc[4] += f2.x; acc[5] += f2.y; acc[6] += f3.x; acc[7] += f3.y;
        }
    }
    for (; k < deg; k++) {
        int j = __ldg(nb + k);
        uint4 rv = *(const uint4*)(src + (size_t)j * OUTF + c);
        float2 f0 = __half22float2(*(__half2*)&rv.x);
        float2 f1 = __half22float2(*(__half2*)&rv.y);
        float2 f2 = __half22float2(*(__half2*)&rv.z);
        float2 f3 = __half22float2(*(__half2*)&rv.w);
        acc[0] += f0.x; acc[1] += f0.y; acc[2] += f1.x; acc[3] += f1.y;
        acc[4] += f2.x; acc[5] += f2.y; acc[6] += f3.x; acc[7] += f3.y;
    }

    float4 b0 = *(const float4*)(bias + c);
    float4 b1 = *(const float4*)(bias + c + 4);
    float* op = out + (size_t)row * OUTF + c;
    *(float4*)(op)     = make_float4(acc[0] + b0.x, acc[1] + b0.y, acc[2] + b0.z, acc[3] + b0.w);
    *(float4*)(op + 4) = make_float4(acc[4] + b1.x, acc[5] + b1.y, acc[6] + b1.z, acc[7] + b1.w);
}

// ---------------- launcher --------------------------------------------------
extern "C" void kernel_launch(void* const* d_in, const int* in_sizes, int n_in,
                              void* d_out, int out_size) {
    const float* x    = (const float*)d_in[0];
    const float* adj  = (const float*)d_in[1];
    const float* W1   = (const float*)d_in[2];
    const float* a1   = (const float*)d_in[3];
    const float* W2   = (const float*)d_in[4];
    const float* a2   = (const float*)d_in[5];
    const float* Wsgc = (const float*)d_in[6];
    const float* bsgc = (const float*)d_in[7];
    float* out = (float*)d_out;

    k_prelude<<<6912, 256>>>(adj, x, W1, a1, Wsgc);
    k_gemm_gat1<<<768, 256>>>(W2, a2);    // v=x@WA, u=x@WC || gat1
    k_z1_mask<<<1024, 256>>>();           // z1 = A@u || mask
    k_z2<<<512, 256>>>();                 // z2 = A@z1
    k_out<<<512, 256>>>(bsgc, out);       // out = routed hop + bias
}

// round 10
// speedup vs baseline: 3.0950x; 1.1030x over previous
#include <cuda_runtime.h>
#include <cuda_fp16.h>
#include <mma.h>
#include <math.h>

using namespace nvcuda;

#define NN    4096
#define INF_  512
#define HID   8
#define OUTF  256
#define MAXD  128

// ---------------- scratch (static device globals) ---------------------------
__device__ int    g_deg[NN];
__device__ int    g_nbr[NN * MAXD];
__device__ float  g_phu[NN * HID];    // exp(dst1[j]) * h[j]   (unnormalized)
__device__ float  g_e1[NN];           // exp(dst1[j])
__device__ float  g_qu[NN];           // exp(d2[j]) * h2v[j]   (unnormalized)
__device__ float  g_e2[NN];           // exp(d2[j])
__device__ int    g_mask1[NN];        // 1 -> row uses A@v (W_A path)
__device__ __half g_xh[NN * INF_];    // x in fp16
__device__ __half g_v [NN * OUTF];    // x @ W_A   (for mask==1 rows)
__device__ __half g_u [NN * OUTF];    // x @ W_C   (for mask==0 rows)
__device__ __half g_z1[NN * OUTF];    // A @ u
__device__ __half g_z2[NN * OUTF];    // A^2 @ u
__device__ __half g_WhA[INF_ * OUTF]; // W_sgc[0:512]     in fp16
__device__ __half g_WhC[INF_ * OUTF]; // W_sgc[1024:1536] in fp16

// ---- fused prelude: build nbr lists | x->fp16 | h=x@W1 chain | W->fp16 -----
__global__ void k_prelude(const float* __restrict__ adj, const float* __restrict__ x,
                          const float* __restrict__ W1, const float* __restrict__ a1,
                          const float* __restrict__ Wsgc) {
    int b = blockIdx.x;
    int t = threadIdx.x;          // 256

    if (b < 4096) {
        int row = b;
        const float4* ar = (const float4*)(adj + (size_t)row * NN);
        float4 v[4];
        int cnt = 0;
#pragma unroll
        for (int i = 0; i < 4; i++) {
            v[i] = ar[t + i * 256];
            cnt += (v[i].x != 0.f) + (v[i].y != 0.f) + (v[i].z != 0.f) + (v[i].w != 0.f);
        }
        __shared__ int sc[256];
        sc[t] = cnt;
        __syncthreads();
        for (int d = 1; d < 256; d <<= 1) {
            int val = (t >= d) ? sc[t - d] : 0;
            __syncthreads();
            if (t >= d) sc[t] += val;
            __syncthreads();
        }
        int pos   = sc[t] - cnt;
        int total = sc[255];
        int* nb = g_nbr + (size_t)row * MAXD;
#pragma unroll
        for (int i = 0; i < 4; i++) {
            int base = (t + i * 256) * 4;
            if (v[i].x != 0.f) { if (pos < MAXD) nb[pos] = base + 0; pos++; }
            if (v[i].y != 0.f) { if (pos < MAXD) nb[pos] = base + 1; pos++; }
            if (v[i].z != 0.f) { if (pos < MAXD) nb[pos] = base + 2; pos++; }
            if (v[i].w != 0.f) { if (pos < MAXD) nb[pos] = base + 3; pos++; }
        }
        if (t == 0) g_deg[row] = total < MAXD ? total : MAXD;
    } else if (b < 6144) {
        int i = (b - 4096) * 256 + t;
        float4 v = ((const float4*)x)[i];
        __half2 lo = __floats2half2_rn(v.x, v.y);
        __half2 hi = __floats2half2_rn(v.z, v.w);
        uint2 packed;
        packed.x = *(unsigned*)&lo;
        packed.y = *(unsigned*)&hi;
        ((uint2*)g_xh)[i] = packed;
    } else if (b < 6656) {
        int lane = t & 31;
        int row  = (b - 6144) * 8 + (t >> 5);
        const float* xr = x + (size_t)row * INF_;
        float acc[HID];
#pragma unroll
        for (int f = 0; f < HID; f++) acc[f] = 0.f;
        for (int k = lane; k < INF_; k += 32) {
            float xv = xr[k];
            float4 wA = *(const float4*)(W1 + k * HID);
            float4 wB = *(const float4*)(W1 + k * HID + 4);
            acc[0] += xv * wA.x; acc[1] += xv * wA.y; acc[2] += xv * wA.z; acc[3] += xv * wA.w;
            acc[4] += xv * wB.x; acc[5] += xv * wB.y; acc[6] += xv * wB.z; acc[7] += xv * wB.w;
        }
#pragma unroll
        for (int f = 0; f < HID; f++)
            for (int o = 16; o; o >>= 1) acc[f] += __shfl_xor_sync(0xffffffffu, acc[f], o);
        if (lane == 0) {
            float d = 0.f;
#pragma unroll
            for (int f = 0; f < HID; f++) d += acc[f] * a1[HID + f];
            float e1 = expf(d);
            g_e1[row] = e1;
#pragma unroll
            for (int f = 0; f < HID; f++) g_phu[row * HID + f] = e1 * acc[f];
        }
    } else {
        int which = (b >= 6784);
        int base  = which ? 6784 : 6656;
        const float* src = Wsgc + (which ? (size_t)1024 * OUTF : 0);
        __half* dst = which ? g_WhC : g_WhA;
        int i = (b - base) * 256 + t;
        float4 v = ((const float4*)src)[i];
        __half2 lo = __floats2half2_rn(v.x, v.y);
        __half2 hi = __floats2half2_rn(v.z, v.w);
        uint2 packed;
        packed.x = *(unsigned*)&lo;
        packed.y = *(unsigned*)&hi;
        ((uint2*)dst)[i] = packed;
    }
}

// ---- block-redundant sum of 4096 floats (deterministic order) --------------
__device__ __forceinline__ float block_sum4096(const float* v, int t) {
    __shared__ float sred[8];
    __shared__ float sbc;
    float s = 0.f;
    const float4* v4 = (const float4*)v;
#pragma unroll
    for (int i = 0; i < 4; i++) {
        float4 a = v4[t + i * 256];
        s += (a.x + a.y) + (a.z + a.w);
    }
    for (int o = 16; o; o >>= 1) s += __shfl_xor_sync(0xffffffffu, s, o);
    if ((t & 31) == 0) sred[t >> 5] = s;
    __syncthreads();
    if (t < 32) {
        float r = (t < 8) ? sred[t] : 0.f;
        for (int o = 4; o; o >>= 1) r += __shfl_xor_sync(0xffffffffu, r, o);
        if (t == 0) sbc = r;
    }
    __syncthreads();
    return sbc;
}

// ---- gat1 body: h1=elu((adj@phu)/S1); h2=h1@W2; e2=exp(h2*a2[1]); qu=e2*h2 -
__device__ __forceinline__ void gat1_body(int blk, const float* __restrict__ W2,
                                          const float* __restrict__ a2) {
    int t    = threadIdx.x;
    float S1 = block_sum4096(g_e1, t);

    int lane = t & 31;
    int row  = blk * 8 + (t >> 5);
    int deg  = g_deg[row];
    const int* nb = g_nbr + (size_t)row * MAXD;

    float acc[HID];
#pragma unroll
    for (int f = 0; f < HID; f++) acc[f] = 0.f;

    for (int k = lane; k < deg; k += 32) {
        int j = nb[k];
        float4 A = *(const float4*)(g_phu + j * HID);
        float4 B = *(const float4*)(g_phu + j * HID + 4);
        acc[0] += A.x; acc[1] += A.y; acc[2] += A.z; acc[3] += A.w;
        acc[4] += B.x; acc[5] += B.y; acc[6] += B.z; acc[7] += B.w;
    }
#pragma unroll
    for (int f = 0; f < HID; f++)
        for (int o = 16; o; o >>= 1) acc[f] += __shfl_xor_sync(0xffffffffu, acc[f], o);

    if (lane == 0) {
        float invS = 1.f / S1;
        float h2 = 0.f;
#pragma unroll
        for (int f = 0; f < HID; f++) {
            float v = acc[f] * invS;
            v = v > 0.f ? v : (expf(v) - 1.f);   // elu
            h2 += v * W2[f];
        }
        float e2 = expf(h2 * a2[1]);
        g_e2[row] = e2;
        g_qu[row] = e2 * h2;
    }
}

// ---- mask body: s2=(adj@qu)/S2; elu; threshold -> g_mask1 ------------------
__device__ __forceinline__ void mask_body(int blk) {
    int t    = threadIdx.x;
    float S2 = block_sum4096(g_e2, t);

    int lane = t & 31;
    int row  = blk * 8 + (t >> 5);
    int deg  = g_deg[row];
    const int* nb = g_nbr + (size_t)row * MAXD;

    float s = 0.f;
    for (int k = lane; k < deg; k += 32) s += g_qu[nb[k]];
    for (int o = 16; o; o >>= 1) s += __shfl_xor_sync(0xffffffffu, s, o);

    if (lane == 0) {
        float s2 = s / S2;
        float sc = s2 > 0.f ? s2 : (expf(s2) - 1.f);   // elu
        g_mask1[row] = (sc > 0.7f) ? 1 : 0;
    }
}

// ---- dense GEMM body: dst[4096x256] = xh @ Wh (fp16 out, fp32 acc) ---------
#define GLDA_S 72    // halves (64 + 8 pad)
#define GLDB_S 136   // halves (128 + 8 pad)
#define GLDS_F 132   // floats (128 + 4 pad)

__device__ __forceinline__ void gemm_dense(int which, int bx, int by) {
    __shared__ __align__(16) char buf[64 * GLDS_F * 4];

    __half* sA = (__half*)buf;
    __half* sB = (__half*)(buf + 64 * GLDA_S * 2);
    float*  stage = (float*)buf;

    const __half* W   = which ? g_WhC : g_WhA;
    __half*       dst = which ? g_u   : g_v;
    int rbase = bx * 64;
    int cb    = by * 128;

    int t = threadIdx.x;   // 256
    int warp = t >> 5;
    int wrow = warp & 3;
    int wcol = warp >> 2;

    const __half* aSrc = g_xh + (size_t)(rbase + (t >> 2)) * INF_;
    int apart = t & 3;

    wmma::fragment<wmma::accumulator, 16, 16, 16, float> cfr[4];
#pragma unroll
    for (int j = 0; j < 4; j++) wmma::fill_fragment(cfr[j], 0.f);

    for (int kc = 0; kc < INF_; kc += 64) {
#pragma unroll
        for (int u = 0; u < 2; u++) {
            int chunk = apart * 2 + u;
            uint4 v = *(const uint4*)(aSrc + kc + chunk * 8);
            *(uint4*)(sA + (t >> 2) * GLDA_S + chunk * 8) = v;
        }
#pragma unroll
        for (int v4 = 0; v4 < 4; v4++) {
            int idx = v4 * 256 + t;
            int krow = idx >> 4, chunk = idx & 15;
            uint4 v = *(const uint4*)(W + (size_t)(kc + krow) * OUTF + cb + chunk * 8);
            *(uint4*)(sB + krow * GLDB_S + chunk * 8) = v;
        }
        __syncthreads();

#pragma unroll
        for (int ks = 0; ks < 4; ks++) {
            wmma::fragment<wmma::matrix_a, 16, 16, 16, __half, wmma::row_major> afr;
            wmma::load_matrix_sync(afr, sA + wrow * 16 * GLDA_S + ks * 16, GLDA_S);
#pragma unroll
            for (int j = 0; j < 4; j++) {
                wmma::fragment<wmma::matrix_b, 16, 16, 16, __half, wmma::row_major> bfr;
                wmma::load_matrix_sync(bfr, sB + ks * 16 * GLDB_S + wcol * 64 + j * 16, GLDB_S);
                wmma::mma_sync(cfr[j], afr, bfr, cfr[j]);
            }
        }
        __syncthreads();
    }

#pragma unroll
    for (int j = 0; j < 4; j++)
        wmma::store_matrix_sync(stage + wrow * 16 * GLDS_F + wcol * 64 + j * 16,
                                cfr[j], GLDS_F, wmma::mem_row_major);
    __syncthreads();

#pragma unroll
    for (int w = 0; w < 8; w++) {
        int idx = w * 256 + t;            // 0..2047, 4 cols each
        int rl = idx >> 5, chunk = idx & 31;
        int col = chunk * 4;
        float4 v = *(const float4*)(stage + rl * GLDS_F + col);
        __half2 h0 = __floats2half2_rn(v.x, v.y);
        __half2 h1 = __floats2half2_rn(v.z, v.w);
        uint2 p;
        p.x = *(unsigned*)&h0;
        p.y = *(unsigned*)&h1;
        *(uint2*)(dst + (size_t)(rbase + rl) * OUTF + cb + col) = p;
    }
}

// ---- SpMM 128-col half: warp per (row, col-half), uint2 (8B)/thread --------
__device__ __forceinline__ void spmm128(const __half* __restrict__ src,
                                        __half* __restrict__ dst,
                                        int blk, int ch) {
    int wid  = threadIdx.x >> 5;
    int lane = threadIdx.x & 31;
    int row  = blk * 8 + wid;
    int deg  = g_deg[row];
    const int* __restrict__ nb = g_nbr + (size_t)row * MAXD;

    int c = ch * 128 + (lane << 2);   // 32 thr * 4 halves = 128 cols
    float acc[4];
#pragma unroll
    for (int i = 0; i < 4; i++) acc[i] = 0.f;

    int k = 0;
    for (; k + 8 <= deg; k += 8) {
        int j[8];
#pragma unroll
        for (int u = 0; u < 8; u++) j[u] = __ldg(nb + k + u);
        uint2 r[8];
#pragma unroll
        for (int u = 0; u < 8; u++)
            r[u] = *(const uint2*)(src + (size_t)j[u] * OUTF + c);
#pragma unroll
        for (int u = 0; u < 8; u++) {
            float2 f0 = __half22float2(*(__half2*)&r[u].x);
            float2 f1 = __half22float2(*(__half2*)&r[u].y);
            acc[0] += f0.x; acc[1] += f0.y; acc[2] += f1.x; acc[3] += f1.y;
        }
    }
    for (; k < deg; k++) {
        int j = __ldg(nb + k);
        uint2 rv = *(const uint2*)(src + (size_t)j * OUTF + c);
        float2 f0 = __half22float2(*(__half2*)&rv.x);
        float2 f1 = __half22float2(*(__half2*)&rv.y);
        acc[0] += f0.x; acc[1] += f0.y; acc[2] += f1.x; acc[3] += f1.y;
    }

    uint2 packed;
    __half2 h0 = __floats2half2_rn(acc[0], acc[1]);
    __half2 h1 = __floats2half2_rn(acc[2], acc[3]);
    packed.x = *(unsigned*)&h0;
    packed.y = *(unsigned*)&h1;
    *(uint2*)(dst + (size_t)row * OUTF + c) = packed;
}

// ---- L2: dense GEMMs u,v [0,256) | gat1 [256,768) --------------------------
__global__ void k_gemm_gat1(const float* __restrict__ W2, const float* __restrict__ a2) {
    int b = blockIdx.x;
    if (b < 256) {
        int which = b >> 7;            // 0: v=x@WA, 1: u=x@WC
        int tile  = b & 127;
        gemm_dense(which, tile >> 1, tile & 1);
    } else {
        gat1_body(b - 256, W2, a2);
    }
}

// ---- L3: z1 = A@u [0,1024) | mask [1024,1536) ------------------------------
__global__ void k_z1_mask() {
    int b = blockIdx.x;
    if (b < 1024) spmm128(g_u, g_z1, b >> 1, b & 1);
    else          mask_body(b - 1024);
}

// ---- L4: z2 = A@z1 (grid 512 x 2) ------------------------------------------
__global__ void k_z2() {
    spmm128(g_z1, g_z2, blockIdx.x, blockIdx.y);
}

// ---- L5: out[r] = (mask1 ? A@v : A@z2)[r] + bias (fp32), grid 512 x 2 ------
__global__ void k_out(const float* __restrict__ bias, float* __restrict__ out) {
    int wid  = threadIdx.x >> 5;
    int lane = threadIdx.x & 31;
    int row  = blockIdx.x * 8 + wid;
    int deg  = g_deg[row];
    const int* __restrict__ nb = g_nbr + (size_t)row * MAXD;
    const __half* __restrict__ src = g_mask1[row] ? g_v : g_z2;

    int c = blockIdx.y * 128 + (lane << 2);
    float acc[4];
#pragma unroll
    for (int i = 0; i < 4; i++) acc[i] = 0.f;

    int k = 0;
    for (; k + 8 <= deg; k += 8) {
        int j[8];
#pragma unroll
        for (int u = 0; u < 8; u++) j[u] = __ldg(nb + k + u);
        uint2 r[8];
#pragma unroll
        for (int u = 0; u < 8; u++)
            r[u] = *(const uint2*)(src + (size_t)j[u] * OUTF + c);
#pragma unroll
        for (int u = 0; u < 8; u++) {
            float2 f0 = __half22float2(*(__half2*)&r[u].x);
            float2 f1 = __half22float2(*(__half2*)&r[u].y);
            acc[0] += f0.x; acc[1] += f0.y; acc[2] += f1.x; acc[3] += f1.y;
        }
    }
    for (; k < deg; k++) {
        int j = __ldg(nb + k);
        uint2 rv = *(const uint2*)(src + (size_t)j * OUTF + c);
        float2 f0 = __half22float2(*(__half2*)&rv.x);
        float2 f1 = __half22float2(*(__half2*)&rv.y);
        acc[0] += f0.x; acc[1] += f0.y; acc[2] += f1.x; acc[3] += f1.y;
    }

    float4 b0 = *(const float4*)(bias + c);
    *(float4*)(out + (size_t)row * OUTF + c) =
        make_float4(acc[0] + b0.x, acc[1] + b0.y, acc[2] + b0.z, acc[3] + b0.w);
}

// ---------------- launcher --------------------------------------------------
extern "C" void kernel_launch(void* const* d_in, const int* in_sizes, int n_in,
                              void* d_out, int out_size) {
    const float* x    = (const float*)d_in[0];
    const float* adj  = (const float*)d_in[1];
    const float* W1   = (const float*)d_in[2];
    const float* a1   = (const float*)d_in[3];
    const float* W2   = (const float*)d_in[4];
    const float* a2   = (const float*)d_in[5];
    const float* Wsgc = (const float*)d_in[6];
    const float* bsgc = (const float*)d_in[7];
    float* out = (float*)d_out;

    k_prelude<<<6912, 256>>>(adj, x, W1, a1, Wsgc);
    k_gemm_gat1<<<768, 256>>>(W2, a2);        // v=x@WA, u=x@WC || gat1
    k_z1_mask<<<1536, 256>>>();               // z1 = A@u || mask
    k_z2<<<dim3(512, 2), 256>>>();            // z2 = A@z1
    k_out<<<dim3(512, 2), 256>>>(bsgc, out);  // out = routed hop + bias
}

// round 11
// speedup vs baseline: 3.1060x; 1.0036x over previous
#include <cuda_runtime.h>
#include <cuda_fp16.h>
#include <mma.h>
#include <math.h>

using namespace nvcuda;

#define NN    4096
#define INF_  512
#define HID   8
#define OUTF  256
#define MAXD  128

// ---------------- scratch (static device globals) ---------------------------
__device__ int    g_deg[NN];
__device__ int    g_nbr[NN * MAXD];
__device__ float  g_phu[NN * HID];    // exp(dst1[j]) * h[j]   (unnormalized)
__device__ float  g_e1[NN];           // exp(dst1[j])
__device__ float  g_qu[NN];           // exp(d2[j]) * h2v[j]   (unnormalized)
__device__ float  g_e2[NN];           // exp(d2[j])
__device__ int    g_mask1[NN];        // 1 -> row uses A@v (W_A path)
__device__ __half g_xh[NN * INF_];    // x in fp16
__device__ __half g_v [NN * OUTF];    // x @ W_A   (for mask==1 rows)
__device__ __half g_u [NN * OUTF];    // x @ W_C   (for mask==0 rows)
__device__ __half g_z1[NN * OUTF];    // A @ u
__device__ __half g_z2[NN * OUTF];    // A^2 @ u
__device__ __half g_WhA[INF_ * OUTF]; // W_sgc[0:512]     in fp16
__device__ __half g_WhC[INF_ * OUTF]; // W_sgc[1024:1536] in fp16

// ---- fused prelude: build nbr lists | x->fp16 | h=x@W1 chain | W->fp16 -----
__global__ void k_prelude(const float* __restrict__ adj, const float* __restrict__ x,
                          const float* __restrict__ W1, const float* __restrict__ a1,
                          const float* __restrict__ Wsgc) {
    int b = blockIdx.x;
    int t = threadIdx.x;          // 256

    if (b < 4096) {
        int row = b;
        const float4* ar = (const float4*)(adj + (size_t)row * NN);
        float4 v[4];
        int cnt = 0;
#pragma unroll
        for (int i = 0; i < 4; i++) {
            v[i] = ar[t + i * 256];
            cnt += (v[i].x != 0.f) + (v[i].y != 0.f) + (v[i].z != 0.f) + (v[i].w != 0.f);
        }
        __shared__ int sc[256];
        sc[t] = cnt;
        __syncthreads();
        for (int d = 1; d < 256; d <<= 1) {
            int val = (t >= d) ? sc[t - d] : 0;
            __syncthreads();
            if (t >= d) sc[t] += val;
            __syncthreads();
        }
        int pos   = sc[t] - cnt;
        int total = sc[255];
        int* nb = g_nbr + (size_t)row * MAXD;
#pragma unroll
        for (int i = 0; i < 4; i++) {
            int base = (t + i * 256) * 4;
            if (v[i].x != 0.f) { if (pos < MAXD) nb[pos] = base + 0; pos++; }
            if (v[i].y != 0.f) { if (pos < MAXD) nb[pos] = base + 1; pos++; }
            if (v[i].z != 0.f) { if (pos < MAXD) nb[pos] = base + 2; pos++; }
            if (v[i].w != 0.f) { if (pos < MAXD) nb[pos] = base + 3; pos++; }
        }
        if (t == 0) g_deg[row] = total < MAXD ? total : MAXD;
    } else if (b < 6144) {
        int i = (b - 4096) * 256 + t;
        float4 v = ((const float4*)x)[i];
        __half2 lo = __floats2half2_rn(v.x, v.y);
        __half2 hi = __floats2half2_rn(v.z, v.w);
        uint2 packed;
        packed.x = *(unsigned*)&lo;
        packed.y = *(unsigned*)&hi;
        ((uint2*)g_xh)[i] = packed;
    } else if (b < 6656) {
        int lane = t & 31;
        int row  = (b - 6144) * 8 + (t >> 5);
        const float* xr = x + (size_t)row * INF_;
        float acc[HID];
#pragma unroll
        for (int f = 0; f < HID; f++) acc[f] = 0.f;
        for (int k = lane; k < INF_; k += 32) {
            float xv = xr[k];
            float4 wA = *(const float4*)(W1 + k * HID);
            float4 wB = *(const float4*)(W1 + k * HID + 4);
            acc[0] += xv * wA.x; acc[1] += xv * wA.y; acc[2] += xv * wA.z; acc[3] += xv * wA.w;
            acc[4] += xv * wB.x; acc[5] += xv * wB.y; acc[6] += xv * wB.z; acc[7] += xv * wB.w;
        }
#pragma unroll
        for (int f = 0; f < HID; f++)
            for (int o = 16; o; o >>= 1) acc[f] += __shfl_xor_sync(0xffffffffu, acc[f], o);
        if (lane == 0) {
            float d = 0.f;
#pragma unroll
            for (int f = 0; f < HID; f++) d += acc[f] * a1[HID + f];
            float e1 = expf(d);
            g_e1[row] = e1;
#pragma unroll
            for (int f = 0; f < HID; f++) g_phu[row * HID + f] = e1 * acc[f];
        }
    } else {
        int which = (b >= 6784);
        int base  = which ? 6784 : 6656;
        const float* src = Wsgc + (which ? (size_t)1024 * OUTF : 0);
        __half* dst = which ? g_WhC : g_WhA;
        int i = (b - base) * 256 + t;
        float4 v = ((const float4*)src)[i];
        __half2 lo = __floats2half2_rn(v.x, v.y);
        __half2 hi = __floats2half2_rn(v.z, v.w);
        uint2 packed;
        packed.x = *(unsigned*)&lo;
        packed.y = *(unsigned*)&hi;
        ((uint2*)dst)[i] = packed;
    }
}

// ---- block-redundant sum of 4096 floats (deterministic order) --------------
__device__ __forceinline__ float block_sum4096(const float* v, int t) {
    __shared__ float sred[8];
    __shared__ float sbc;
    float s = 0.f;
    const float4* v4 = (const float4*)v;
#pragma unroll
    for (int i = 0; i < 4; i++) {
        float4 a = v4[t + i * 256];
        s += (a.x + a.y) + (a.z + a.w);
    }
    for (int o = 16; o; o >>= 1) s += __shfl_xor_sync(0xffffffffu, s, o);
    if ((t & 31) == 0) sred[t >> 5] = s;
    __syncthreads();
    if (t < 32) {
        float r = (t < 8) ? sred[t] : 0.f;
        for (int o = 4; o; o >>= 1) r += __shfl_xor_sync(0xffffffffu, r, o);
        if (t == 0) sbc = r;
    }
    __syncthreads();
    return sbc;
}

// ---- gat1 body: h1=elu((adj@phu)/S1); h2=h1@W2; e2=exp(h2*a2[1]); qu=e2*h2 -
__device__ __forceinline__ void gat1_body(int blk, const float* __restrict__ W2,
                                          const float* __restrict__ a2) {
    int t    = threadIdx.x;
    float S1 = block_sum4096(g_e1, t);

    int lane = t & 31;
    int row  = blk * 8 + (t >> 5);
    int deg  = g_deg[row];
    const int* nb = g_nbr + (size_t)row * MAXD;

    float acc[HID];
#pragma unroll
    for (int f = 0; f < HID; f++) acc[f] = 0.f;

    for (int k = lane; k < deg; k += 32) {
        int j = nb[k];
        float4 A = *(const float4*)(g_phu + j * HID);
        float4 B = *(const float4*)(g_phu + j * HID + 4);
        acc[0] += A.x; acc[1] += A.y; acc[2] += A.z; acc[3] += A.w;
        acc[4] += B.x; acc[5] += B.y; acc[6] += B.z; acc[7] += B.w;
    }
#pragma unroll
    for (int f = 0; f < HID; f++)
        for (int o = 16; o; o >>= 1) acc[f] += __shfl_xor_sync(0xffffffffu, acc[f], o);

    if (lane == 0) {
        float invS = 1.f / S1;
        float h2 = 0.f;
#pragma unroll
        for (int f = 0; f < HID; f++) {
            float v = acc[f] * invS;
            v = v > 0.f ? v : (expf(v) - 1.f);   // elu
            h2 += v * W2[f];
        }
        float e2 = expf(h2 * a2[1]);
        g_e2[row] = e2;
        g_qu[row] = e2 * h2;
    }
}

// ---- mask body: s2=(adj@qu)/S2; elu; threshold -> g_mask1 ------------------
__device__ __forceinline__ void mask_body(int blk) {
    int t    = threadIdx.x;
    float S2 = block_sum4096(g_e2, t);

    int lane = t & 31;
    int row  = blk * 8 + (t >> 5);
    int deg  = g_deg[row];
    const int* nb = g_nbr + (size_t)row * MAXD;

    float s = 0.f;
    for (int k = lane; k < deg; k += 32) s += g_qu[nb[k]];
    for (int o = 16; o; o >>= 1) s += __shfl_xor_sync(0xffffffffu, s, o);

    if (lane == 0) {
        float s2 = s / S2;
        float sc = s2 > 0.f ? s2 : (expf(s2) - 1.f);   // elu
        g_mask1[row] = (sc > 0.7f) ? 1 : 0;
    }
}

// ---- dense GEMM body: dst[4096x256] = xh @ Wh (fp16 out, fp32 acc) ---------
#define GLDA_S 72    // halves (64 + 8 pad)
#define GLDB_S 136   // halves (128 + 8 pad)
#define GLDS_F 132   // floats (128 + 4 pad)

__device__ __forceinline__ void gemm_dense(int which, int bx, int by) {
    __shared__ __align__(16) char buf[64 * GLDS_F * 4];

    __half* sA = (__half*)buf;
    __half* sB = (__half*)(buf + 64 * GLDA_S * 2);
    float*  stage = (float*)buf;

    const __half* W   = which ? g_WhC : g_WhA;
    __half*       dst = which ? g_u   : g_v;
    int rbase = bx * 64;
    int cb    = by * 128;

    int t = threadIdx.x;   // 256
    int warp = t >> 5;
    int wrow = warp & 3;
    int wcol = warp >> 2;

    const __half* aSrc = g_xh + (size_t)(rbase + (t >> 2)) * INF_;
    int apart = t & 3;

    wmma::fragment<wmma::accumulator, 16, 16, 16, float> cfr[4];
#pragma unroll
    for (int j = 0; j < 4; j++) wmma::fill_fragment(cfr[j], 0.f);

    for (int kc = 0; kc < INF_; kc += 64) {
#pragma unroll
        for (int u = 0; u < 2; u++) {
            int chunk = apart * 2 + u;
            uint4 v = *(const uint4*)(aSrc + kc + chunk * 8);
            *(uint4*)(sA + (t >> 2) * GLDA_S + chunk * 8) = v;
        }
#pragma unroll
        for (int v4 = 0; v4 < 4; v4++) {
            int idx = v4 * 256 + t;
            int krow = idx >> 4, chunk = idx & 15;
            uint4 v = *(const uint4*)(W + (size_t)(kc + krow) * OUTF + cb + chunk * 8);
            *(uint4*)(sB + krow * GLDB_S + chunk * 8) = v;
        }
        __syncthreads();

#pragma unroll
        for (int ks = 0; ks < 4; ks++) {
            wmma::fragment<wmma::matrix_a, 16, 16, 16, __half, wmma::row_major> afr;
            wmma::load_matrix_sync(afr, sA + wrow * 16 * GLDA_S + ks * 16, GLDA_S);
#pragma unroll
            for (int j = 0; j < 4; j++) {
                wmma::fragment<wmma::matrix_b, 16, 16, 16, __half, wmma::row_major> bfr;
                wmma::load_matrix_sync(bfr, sB + ks * 16 * GLDB_S + wcol * 64 + j * 16, GLDB_S);
                wmma::mma_sync(cfr[j], afr, bfr, cfr[j]);
            }
        }
        __syncthreads();
    }

#pragma unroll
    for (int j = 0; j < 4; j++)
        wmma::store_matrix_sync(stage + wrow * 16 * GLDS_F + wcol * 64 + j * 16,
                                cfr[j], GLDS_F, wmma::mem_row_major);
    __syncthreads();

#pragma unroll
    for (int w = 0; w < 8; w++) {
        int idx = w * 256 + t;            // 0..2047, 4 cols each
        int rl = idx >> 5, chunk = idx & 31;
        int col = chunk * 4;
        float4 v = *(const float4*)(stage + rl * GLDS_F + col);
        __half2 h0 = __floats2half2_rn(v.x, v.y);
        __half2 h1 = __floats2half2_rn(v.z, v.w);
        uint2 p;
        p.x = *(unsigned*)&h0;
        p.y = *(unsigned*)&h1;
        *(uint2*)(dst + (size_t)(rbase + rl) * OUTF + cb + col) = p;
    }
}

// ---- SpMM 128-col half: warp per (row, col-half), uint2 (8B)/thread --------
__device__ __forceinline__ void spmm128(const __half* __restrict__ src,
                                        __half* __restrict__ dst,
                                        int blk, int ch) {
    int wid  = threadIdx.x >> 5;
    int lane = threadIdx.x & 31;
    int row  = blk * 8 + wid;
    int deg  = g_deg[row];
    const int* __restrict__ nb = g_nbr + (size_t)row * MAXD;

    int c = ch * 128 + (lane << 2);   // 32 thr * 4 halves = 128 cols
    float acc[4];
#pragma unroll
    for (int i = 0; i < 4; i++) acc[i] = 0.f;

    int k = 0;
    for (; k + 8 <= deg; k += 8) {
        int j[8];
#pragma unroll
        for (int u = 0; u < 8; u++) j[u] = __ldg(nb + k + u);
        uint2 r[8];
#pragma unroll
        for (int u = 0; u < 8; u++)
            r[u] = *(const uint2*)(src + (size_t)j[u] * OUTF + c);
#pragma unroll
        for (int u = 0; u < 8; u++) {
            float2 f0 = __half22float2(*(__half2*)&r[u].x);
            float2 f1 = __half22float2(*(__half2*)&r[u].y);
            acc[0] += f0.x; acc[1] += f0.y; acc[2] += f1.x; acc[3] += f1.y;
        }
    }
    for (; k < deg; k++) {
        int j = __ldg(nb + k);
        uint2 rv = *(const uint2*)(src + (size_t)j * OUTF + c);
        float2 f0 = __half22float2(*(__half2*)&rv.x);
        float2 f1 = __half22float2(*(__half2*)&rv.y);
        acc[0] += f0.x; acc[1] += f0.y; acc[2] += f1.x; acc[3] += f1.y;
    }

    uint2 packed;
    __half2 h0 = __floats2half2_rn(acc[0], acc[1]);
    __half2 h1 = __floats2half2_rn(acc[2], acc[3]);
    packed.x = *(unsigned*)&h0;
    packed.y = *(unsigned*)&h1;
    *(uint2*)(dst + (size_t)row * OUTF + c) = packed;
}

// ---- routed-output body: out[row] = gather(src) + bias, for mask==sel ------
__device__ __forceinline__ void out_body(int blk, int ch, int sel,
                                         const float* __restrict__ bias,
                                         float* __restrict__ out) {
    int wid  = threadIdx.x >> 5;
    int lane = threadIdx.x & 31;
    int row  = blk * 8 + wid;
    if (g_mask1[row] != sel) return;          // other launch handles this row
    int deg  = g_deg[row];
    const int* __restrict__ nb = g_nbr + (size_t)row * MAXD;
    const __half* __restrict__ src = sel ? g_v : g_z2;

    int c = ch * 128 + (lane << 2);
    float acc[4];
#pragma unroll
    for (int i = 0; i < 4; i++) acc[i] = 0.f;

    int k = 0;
    for (; k + 8 <= deg; k += 8) {
        int j[8];
#pragma unroll
        for (int u = 0; u < 8; u++) j[u] = __ldg(nb + k + u);
        uint2 r[8];
#pragma unroll
        for (int u = 0; u < 8; u++)
            r[u] = *(const uint2*)(src + (size_t)j[u] * OUTF + c);
#pragma unroll
        for (int u = 0; u < 8; u++) {
            float2 f0 = __half22float2(*(__half2*)&r[u].x);
            float2 f1 = __half22float2(*(__half2*)&r[u].y);
            acc[0] += f0.x; acc[1] += f0.y; acc[2] += f1.x; acc[3] += f1.y;
        }
    }
    for (; k < deg; k++) {
        int j = __ldg(nb + k);
        uint2 rv = *(const uint2*)(src + (size_t)j * OUTF + c);
        float2 f0 = __half22float2(*(__half2*)&rv.x);
        float2 f1 = __half22float2(*(__half2*)&rv.y);
        acc[0] += f0.x; acc[1] += f0.y; acc[2] += f1.x; acc[3] += f1.y;
    }

    float4 b0 = *(const float4*)(bias + c);
    *(float4*)(out + (size_t)row * OUTF + c) =
        make_float4(acc[0] + b0.x, acc[1] + b0.y, acc[2] + b0.z, acc[3] + b0.w);
}

// ---- L2: dense GEMMs u,v [0,256) | gat1 [256,768) --------------------------
__global__ void k_gemm_gat1(const float* __restrict__ W2, const float* __restrict__ a2) {
    int b = blockIdx.x;
    if (b < 256) {
        int which = b >> 7;            // 0: v=x@WA, 1: u=x@WC
        int tile  = b & 127;
        gemm_dense(which, tile >> 1, tile & 1);
    } else {
        gat1_body(b - 256, W2, a2);
    }
}

// ---- L3: z1 = A@u [0,1024) | mask [1024,1536) ------------------------------
__global__ void k_z1_mask() {
    int b = blockIdx.x;
    if (b < 1024) spmm128(g_u, g_z1, b >> 1, b & 1);
    else          mask_body(b - 1024);
}

// ---- L4: z2 = A@z1 [0,1024) | out for mask==1 rows [1024,2048) -------------
__global__ void k_z2_out1(const float* __restrict__ bias, float* __restrict__ out) {
    int b = blockIdx.x;
    if (b < 1024) spmm128(g_z1, g_z2, b >> 1, b & 1);
    else {
        int bb = b - 1024;
        out_body(bb >> 1, bb & 1, 1, bias, out);
    }
}

// ---- L5: out for mask==0 rows (needs z2) -----------------------------------
__global__ void k_out0(const float* __restrict__ bias, float* __restrict__ out) {
    out_body(blockIdx.x, blockIdx.y, 0, bias, out);
}

// ---------------- launcher --------------------------------------------------
extern "C" void kernel_launch(void* const* d_in, const int* in_sizes, int n_in,
                              void* d_out, int out_size) {
    const float* x    = (const float*)d_in[0];
    const float* adj  = (const float*)d_in[1];
    const float* W1   = (const float*)d_in[2];
    const float* a1   = (const float*)d_in[3];
    const float* W2   = (const float*)d_in[4];
    const float* a2   = (const float*)d_in[5];
    const float* Wsgc = (const float*)d_in[6];
    const float* bsgc = (const float*)d_in[7];
    float* out = (float*)d_out;

    k_prelude<<<6912, 256>>>(adj, x, W1, a1, Wsgc);
    k_gemm_gat1<<<768, 256>>>(W2, a2);          // v=x@WA, u=x@WC || gat1
    k_z1_mask<<<1536, 256>>>();                 // z1 = A@u || mask
    k_z2_out1<<<2048, 256>>>(bsgc, out);        // z2 = A@z1 || out(mask1)
    k_out0<<<dim3(512, 2), 256>>>(bsgc, out);   // out(mask0)
}

// round 12
// speedup vs baseline: 3.1555x; 1.0159x over previous
#include <cuda_runtime.h>
#include <cuda_fp16.h>
#include <mma.h>
#include <math.h>

using namespace nvcuda;

#define NN    4096
#define INF_  512
#define HID   8
#define OUTF  256
#define MAXD  128

#define H2REF(u) (*(__half2*)&(u))

// ---------------- scratch (static device globals) ---------------------------
__device__ int    g_deg[NN];
__device__ int    g_nbr[NN * MAXD];
__device__ float  g_phu[NN * HID];    // exp(dst1[j]) * h[j]   (unnormalized)
__device__ float  g_e1[NN];           // exp(dst1[j])
__device__ float  g_qu[NN];           // exp(d2[j]) * h2v[j]   (unnormalized)
__device__ float  g_e2[NN];           // exp(d2[j])
__device__ int    g_mask1[NN];        // 1 -> row uses A@v (W_A path)
__device__ __half g_xh[NN * INF_];    // x in fp16
__device__ __half g_v [NN * OUTF];    // x @ W_A   (for mask==1 rows)
__device__ __half g_u [NN * OUTF];    // x @ W_C   (for mask==0 rows)
__device__ __half g_z1[NN * OUTF];    // A @ u
__device__ __half g_z2[NN * OUTF];    // A^2 @ u
__device__ __half g_WhA[INF_ * OUTF]; // W_sgc[0:512]     in fp16
__device__ __half g_WhC[INF_ * OUTF]; // W_sgc[1024:1536] in fp16

// ---- fused prelude: build nbr lists | x->fp16 | h=x@W1 chain | W->fp16 -----
__global__ void k_prelude(const float* __restrict__ adj, const float* __restrict__ x,
                          const float* __restrict__ W1, const float* __restrict__ a1,
                          const float* __restrict__ Wsgc) {
    int b = blockIdx.x;
    int t = threadIdx.x;          // 256

    if (b < 4096) {
        int row = b;
        const float4* ar = (const float4*)(adj + (size_t)row * NN);
        float4 v[4];
        int cnt = 0;
#pragma unroll
        for (int i = 0; i < 4; i++) {
            v[i] = ar[t + i * 256];
            cnt += (v[i].x != 0.f) + (v[i].y != 0.f) + (v[i].z != 0.f) + (v[i].w != 0.f);
        }
        __shared__ int sc[256];
        sc[t] = cnt;
        __syncthreads();
        for (int d = 1; d < 256; d <<= 1) {
            int val = (t >= d) ? sc[t - d] : 0;
            __syncthreads();
            if (t >= d) sc[t] += val;
            __syncthreads();
        }
        int pos   = sc[t] - cnt;
        int total = sc[255];
        int* nb = g_nbr + (size_t)row * MAXD;
#pragma unroll
        for (int i = 0; i < 4; i++) {
            int base = (t + i * 256) * 4;
            if (v[i].x != 0.f) { if (pos < MAXD) nb[pos] = base + 0; pos++; }
            if (v[i].y != 0.f) { if (pos < MAXD) nb[pos] = base + 1; pos++; }
            if (v[i].z != 0.f) { if (pos < MAXD) nb[pos] = base + 2; pos++; }
            if (v[i].w != 0.f) { if (pos < MAXD) nb[pos] = base + 3; pos++; }
        }
        if (t == 0) g_deg[row] = total < MAXD ? total : MAXD;
    } else if (b < 6144) {
        int i = (b - 4096) * 256 + t;
        float4 v = ((const float4*)x)[i];
        __half2 lo = __floats2half2_rn(v.x, v.y);
        __half2 hi = __floats2half2_rn(v.z, v.w);
        uint2 packed;
        packed.x = *(unsigned*)&lo;
        packed.y = *(unsigned*)&hi;
        ((uint2*)g_xh)[i] = packed;
    } else if (b < 6656) {
        int lane = t & 31;
        int row  = (b - 6144) * 8 + (t >> 5);
        const float* xr = x + (size_t)row * INF_;
        float acc[HID];
#pragma unroll
        for (int f = 0; f < HID; f++) acc[f] = 0.f;
        for (int k = lane; k < INF_; k += 32) {
            float xv = xr[k];
            float4 wA = *(const float4*)(W1 + k * HID);
            float4 wB = *(const float4*)(W1 + k * HID + 4);
            acc[0] += xv * wA.x; acc[1] += xv * wA.y; acc[2] += xv * wA.z; acc[3] += xv * wA.w;
            acc[4] += xv * wB.x; acc[5] += xv * wB.y; acc[6] += xv * wB.z; acc[7] += xv * wB.w;
        }
#pragma unroll
        for (int f = 0; f < HID; f++)
            for (int o = 16; o; o >>= 1) acc[f] += __shfl_xor_sync(0xffffffffu, acc[f], o);
        if (lane == 0) {
            float d = 0.f;
#pragma unroll
            for (int f = 0; f < HID; f++) d += acc[f] * a1[HID + f];
            float e1 = expf(d);
            g_e1[row] = e1;
#pragma unroll
            for (int f = 0; f < HID; f++) g_phu[row * HID + f] = e1 * acc[f];
        }
    } else {
        int which = (b >= 6784);
        int base  = which ? 6784 : 6656;
        const float* src = Wsgc + (which ? (size_t)1024 * OUTF : 0);
        __half* dst = which ? g_WhC : g_WhA;
        int i = (b - base) * 256 + t;
        float4 v = ((const float4*)src)[i];
        __half2 lo = __floats2half2_rn(v.x, v.y);
        __half2 hi = __floats2half2_rn(v.z, v.w);
        uint2 packed;
        packed.x = *(unsigned*)&lo;
        packed.y = *(unsigned*)&hi;
        ((uint2*)dst)[i] = packed;
    }
}

// ---- block-redundant sum of 4096 floats (deterministic order) --------------
__device__ __forceinline__ float block_sum4096(const float* v, int t) {
    __shared__ float sred[8];
    __shared__ float sbc;
    float s = 0.f;
    const float4* v4 = (const float4*)v;
#pragma unroll
    for (int i = 0; i < 4; i++) {
        float4 a = v4[t + i * 256];
        s += (a.x + a.y) + (a.z + a.w);
    }
    for (int o = 16; o; o >>= 1) s += __shfl_xor_sync(0xffffffffu, s, o);
    if ((t & 31) == 0) sred[t >> 5] = s;
    __syncthreads();
    if (t < 32) {
        float r = (t < 8) ? sred[t] : 0.f;
        for (int o = 4; o; o >>= 1) r += __shfl_xor_sync(0xffffffffu, r, o);
        if (t == 0) sbc = r;
    }
    __syncthreads();
    return sbc;
}

// ---- gat1 body: h1=elu((adj@phu)/S1); h2=h1@W2; e2=exp(h2*a2[1]); qu=e2*h2 -
__device__ __forceinline__ void gat1_body(int blk, const float* __restrict__ W2,
                                          const float* __restrict__ a2) {
    int t    = threadIdx.x;
    float S1 = block_sum4096(g_e1, t);

    int lane = t & 31;
    int row  = blk * 8 + (t >> 5);
    int deg  = g_deg[row];
    const int* nb = g_nbr + (size_t)row * MAXD;

    float acc[HID];
#pragma unroll
    for (int f = 0; f < HID; f++) acc[f] = 0.f;

    for (int k = lane; k < deg; k += 32) {
        int j = nb[k];
        float4 A = *(const float4*)(g_phu + j * HID);
        float4 B = *(const float4*)(g_phu + j * HID + 4);
        acc[0] += A.x; acc[1] += A.y; acc[2] += A.z; acc[3] += A.w;
        acc[4] += B.x; acc[5] += B.y; acc[6] += B.z; acc[7] += B.w;
    }
#pragma unroll
    for (int f = 0; f < HID; f++)
        for (int o = 16; o; o >>= 1) acc[f] += __shfl_xor_sync(0xffffffffu, acc[f], o);

    if (lane == 0) {
        float invS = 1.f / S1;
        float h2 = 0.f;
#pragma unroll
        for (int f = 0; f < HID; f++) {
            float v = acc[f] * invS;
            v = v > 0.f ? v : (expf(v) - 1.f);   // elu
            h2 += v * W2[f];
        }
        float e2 = expf(h2 * a2[1]);
        g_e2[row] = e2;
        g_qu[row] = e2 * h2;
    }
}

// ---- mask body: s2=(adj@qu)/S2; elu; threshold -> g_mask1 ------------------
__device__ __forceinline__ void mask_body(int blk) {
    int t    = threadIdx.x;
    float S2 = block_sum4096(g_e2, t);

    int lane = t & 31;
    int row  = blk * 8 + (t >> 5);
    int deg  = g_deg[row];
    const int* nb = g_nbr + (size_t)row * MAXD;

    float s = 0.f;
    for (int k = lane; k < deg; k += 32) s += g_qu[nb[k]];
    for (int o = 16; o; o >>= 1) s += __shfl_xor_sync(0xffffffffu, s, o);

    if (lane == 0) {
        float s2 = s / S2;
        float sc = s2 > 0.f ? s2 : (expf(s2) - 1.f);   // elu
        g_mask1[row] = (sc > 0.7f) ? 1 : 0;
    }
}

// ---- dense GEMM body: dst[4096x256] = xh @ Wh (fp16 out, fp32 acc) ---------
#define GLDA_S 72    // halves (64 + 8 pad)
#define GLDB_S 136   // halves (128 + 8 pad)
#define GLDS_F 132   // floats (128 + 4 pad)

__device__ __forceinline__ void gemm_dense(int which, int bx, int by) {
    __shared__ __align__(16) char buf[64 * GLDS_F * 4];

    __half* sA = (__half*)buf;
    __half* sB = (__half*)(buf + 64 * GLDA_S * 2);
    float*  stage = (float*)buf;

    const __half* W   = which ? g_WhC : g_WhA;
    __half*       dst = which ? g_u   : g_v;
    int rbase = bx * 64;
    int cb    = by * 128;

    int t = threadIdx.x;   // 256
    int warp = t >> 5;
    int wrow = warp & 3;
    int wcol = warp >> 2;

    const __half* aSrc = g_xh + (size_t)(rbase + (t >> 2)) * INF_;
    int apart = t & 3;

    wmma::fragment<wmma::accumulator, 16, 16, 16, float> cfr[4];
#pragma unroll
    for (int j = 0; j < 4; j++) wmma::fill_fragment(cfr[j], 0.f);

    for (int kc = 0; kc < INF_; kc += 64) {
#pragma unroll
        for (int u = 0; u < 2; u++) {
            int chunk = apart * 2 + u;
            uint4 v = *(const uint4*)(aSrc + kc + chunk * 8);
            *(uint4*)(sA + (t >> 2) * GLDA_S + chunk * 8) = v;
        }
#pragma unroll
        for (int v4 = 0; v4 < 4; v4++) {
            int idx = v4 * 256 + t;
            int krow = idx >> 4, chunk = idx & 15;
            uint4 v = *(const uint4*)(W + (size_t)(kc + krow) * OUTF + cb + chunk * 8);
            *(uint4*)(sB + krow * GLDB_S + chunk * 8) = v;
        }
        __syncthreads();

#pragma unroll
        for (int ks = 0; ks < 4; ks++) {
            wmma::fragment<wmma::matrix_a, 16, 16, 16, __half, wmma::row_major> afr;
            wmma::load_matrix_sync(afr, sA + wrow * 16 * GLDA_S + ks * 16, GLDA_S);
#pragma unroll
            for (int j = 0; j < 4; j++) {
                wmma::fragment<wmma::matrix_b, 16, 16, 16, __half, wmma::row_major> bfr;
                wmma::load_matrix_sync(bfr, sB + ks * 16 * GLDB_S + wcol * 64 + j * 16, GLDB_S);
                wmma::mma_sync(cfr[j], afr, bfr, cfr[j]);
            }
        }
        __syncthreads();
    }

#pragma unroll
    for (int j = 0; j < 4; j++)
        wmma::store_matrix_sync(stage + wrow * 16 * GLDS_F + wcol * 64 + j * 16,
                                cfr[j], GLDS_F, wmma::mem_row_major);
    __syncthreads();

#pragma unroll
    for (int w = 0; w < 8; w++) {
        int idx = w * 256 + t;            // 0..2047, 4 cols each
        int rl = idx >> 5, chunk = idx & 31;
        int col = chunk * 4;
        float4 v = *(const float4*)(stage + rl * GLDS_F + col);
        __half2 h0 = __floats2half2_rn(v.x, v.y);
        __half2 h1 = __floats2half2_rn(v.z, v.w);
        uint2 p;
        p.x = *(unsigned*)&h0;
        p.y = *(unsigned*)&h1;
        *(uint2*)(dst + (size_t)(rbase + rl) * OUTF + cb + col) = p;
    }
}

// ---- gather-sum core: fp16 pair-tree (groups of 4), fp32 across groups -----
// acc[0..3] accumulate 4 columns. Deterministic fixed-order.
__device__ __forceinline__ void gather_accum(const __half* __restrict__ src,
                                             const int* __restrict__ nb,
                                             int deg, int c, float* acc) {
    int k = 0;
    for (; k + 8 <= deg; k += 8) {
        int j[8];
#pragma unroll
        for (int u = 0; u < 8; u++) j[u] = __ldg(nb + k + u);
        uint2 r[8];
#pragma unroll
        for (int u = 0; u < 8; u++)
            r[u] = *(const uint2*)(src + (size_t)j[u] * OUTF + c);
        // level 1: pair neighbors in fp16
        __half2 sx01 = __hadd2(H2REF(r[0].x), H2REF(r[1].x));
        __half2 sy01 = __hadd2(H2REF(r[0].y), H2REF(r[1].y));
        __half2 sx23 = __hadd2(H2REF(r[2].x), H2REF(r[3].x));
        __half2 sy23 = __hadd2(H2REF(r[2].y), H2REF(r[3].y));
        __half2 sx45 = __hadd2(H2REF(r[4].x), H2REF(r[5].x));
        __half2 sy45 = __hadd2(H2REF(r[4].y), H2REF(r[5].y));
        __half2 sx67 = __hadd2(H2REF(r[6].x), H2REF(r[7].x));
        __half2 sy67 = __hadd2(H2REF(r[6].y), H2REF(r[7].y));
        // level 2: groups of 4 in fp16
        __half2 tx0 = __hadd2(sx01, sx23);
        __half2 ty0 = __hadd2(sy01, sy23);
        __half2 tx1 = __hadd2(sx45, sx67);
        __half2 ty1 = __hadd2(sy45, sy67);
        // convert groups, accumulate fp32
        float2 f;
        f = __half22float2(tx0); acc[0] += f.x; acc[1] += f.y;
        f = __half22float2(ty0); acc[2] += f.x; acc[3] += f.y;
        f = __half22float2(tx1); acc[0] += f.x; acc[1] += f.y;
        f = __half22float2(ty1); acc[2] += f.x; acc[3] += f.y;
    }
    for (; k < deg; k++) {
        int j = __ldg(nb + k);
        uint2 rv = *(const uint2*)(src + (size_t)j * OUTF + c);
        float2 f0 = __half22float2(H2REF(rv.x));
        float2 f1 = __half22float2(H2REF(rv.y));
        acc[0] += f0.x; acc[1] += f0.y; acc[2] += f1.x; acc[3] += f1.y;
    }
}

// ---- SpMM 128-col half: warp per (row, col-half), uint2 (8B)/thread --------
__device__ __forceinline__ void spmm128(const __half* __restrict__ src,
                                        __half* __restrict__ dst,
                                        int blk, int ch) {
    int wid  = threadIdx.x >> 5;
    int lane = threadIdx.x & 31;
    int row  = blk * 8 + wid;
    int deg  = g_deg[row];
    const int* __restrict__ nb = g_nbr + (size_t)row * MAXD;

    int c = ch * 128 + (lane << 2);   // 32 thr * 4 halves = 128 cols
    float acc[4] = {0.f, 0.f, 0.f, 0.f};
    gather_accum(src, nb, deg, c, acc);

    uint2 packed;
    __half2 h0 = __floats2half2_rn(acc[0], acc[1]);
    __half2 h1 = __floats2half2_rn(acc[2], acc[3]);
    packed.x = *(unsigned*)&h0;
    packed.y = *(unsigned*)&h1;
    *(uint2*)(dst + (size_t)row * OUTF + c) = packed;
}

// ---- routed-output body: out[row] = gather(src) + bias, for mask==sel ------
__device__ __forceinline__ void out_body(int blk, int ch, int sel,
                                         const float* __restrict__ bias,
                                         float* __restrict__ out) {
    int wid  = threadIdx.x >> 5;
    int lane = threadIdx.x & 31;
    int row  = blk * 8 + wid;
    if (g_mask1[row] != sel) return;          // other launch handles this row
    int deg  = g_deg[row];
    const int* __restrict__ nb = g_nbr + (size_t)row * MAXD;
    const __half* __restrict__ src = sel ? g_v : g_z2;

    int c = ch * 128 + (lane << 2);
    float acc[4] = {0.f, 0.f, 0.f, 0.f};
    gather_accum(src, nb, deg, c, acc);

    float4 b0 = *(const float4*)(bias + c);
    *(float4*)(out + (size_t)row * OUTF + c) =
        make_float4(acc[0] + b0.x, acc[1] + b0.y, acc[2] + b0.z, acc[3] + b0.w);
}

// ---- L2: dense GEMMs u,v [0,256) | gat1 [256,768) --------------------------
__global__ void k_gemm_gat1(const float* __restrict__ W2, const float* __restrict__ a2) {
    int b = blockIdx.x;
    if (b < 256) {
        int which = b >> 7;            // 0: v=x@WA, 1: u=x@WC
        int tile  = b & 127;
        gemm_dense(which, tile >> 1, tile & 1);
    } else {
        gat1_body(b - 256, W2, a2);
    }
}

// ---- L3: z1 = A@u [0,1024) | mask [1024,1536) ------------------------------
__global__ void k_z1_mask() {
    int b = blockIdx.x;
    if (b < 1024) spmm128(g_u, g_z1, b >> 1, b & 1);
    else          mask_body(b - 1024);
}

// ---- L4: z2 = A@z1 [0,1024) | out for mask==1 rows [1024,2048) -------------
__global__ void k_z2_out1(const float* __restrict__ bias, float* __restrict__ out) {
    int b = blockIdx.x;
    if (b < 1024) spmm128(g_z1, g_z2, b >> 1, b & 1);
    else {
        int bb = b - 1024;
        out_body(bb >> 1, bb & 1, 1, bias, out);
    }
}

// ---- L5: out for mask==0 rows (needs z2) -----------------------------------
__global__ void k_out0(const float* __restrict__ bias, float* __restrict__ out) {
    out_body(blockIdx.x, blockIdx.y, 0, bias, out);
}

// ---------------- launcher --------------------------------------------------
extern "C" void kernel_launch(void* const* d_in, const int* in_sizes, int n_in,
                              void* d_out, int out_size) {
    const float* x    = (const float*)d_in[0];
    const float* adj  = (const float*)d_in[1];
    const float* W1   = (const float*)d_in[2];
    const float* a1   = (const float*)d_in[3];
    const float* W2   = (const float*)d_in[4];
    const float* a2   = (const float*)d_in[5];
    const float* Wsgc = (const float*)d_in[6];
    const float* bsgc = (const float*)d_in[7];
    float* out = (float*)d_out;

    k_prelude<<<6912, 256>>>(adj, x, W1, a1, Wsgc);
    k_gemm_gat1<<<768, 256>>>(W2, a2);          // v=x@WA, u=x@WC || gat1
    k_z1_mask<<<1536, 256>>>();                 // z1 = A@u || mask
    k_z2_out1<<<2048, 256>>>(bsgc, out);        // z2 = A@z1 || out(mask1)
    k_out0<<<dim3(512, 2), 256>>>(bsgc, out);   // out(mask0)
}